// round 9
// baseline (speedup 1.0000x reference)
#include <cuda_runtime.h>
#include <cuda_bf16.h>
#include <cstdint>
#include <math.h>

#define NE      800000
#define NNODE   50000

// ---------------- scratch (static device arrays; no allocation) ----------------
__device__ float g_UV[(size_t)NNODE * 320];   // [n][0:160]=U=z@W1, [160:320]=V=z@W2
__device__ float g_G1[(size_t)NNODE * 128];   // [n][0:64]=P=z@Wf_top, [64:128]=R=z@Ws_top
__device__ float g_G2[(size_t)NNODE * 128];   // [n][0:64]=Q=z@Wf_bot, [64:128]=S=z@Ws_bot

// ---------------- kernel A (node GEMM, persistent) ----------------
#define A_THR  512
#define A_TILE 64
#define A_NT   ((NNODE + A_TILE - 1) / A_TILE)   // 782
#define A_ZSTR 144
#define A_WSTR 1168
#define A_ZH   0
#define A_ZL   (A_ZH + 64 * A_ZSTR)
#define A_WH   (A_ZL + 64 * A_ZSTR)
#define A_WL   (A_WH + 64 * A_WSTR)
#define A_SMEM (A_WL + 64 * A_WSTR)              // 167936

// ---------------- kernel B (edge assemble + ea@W3) ----------------
#define B_THR  256
#define B_TILE 64
#define B_NT   (NE / B_TILE)                     // 12500
#define B_ESTR 80
#define B_WSTR 336
#define B_TSTR 164                               // floats; 164 mod 32 = 4 -> bank spread
#define B_EH   0
#define B_EL   (B_EH + 64 * B_ESTR)
#define B_WH   (B_EL + 64 * B_ESTR)
#define B_WL   (B_WH + 32 * B_WSTR)
#define B_BIAS (B_WL + 32 * B_WSTR)
#define B_T    (B_BIAS + 640)                    // U[src]+V[dst] staging, 64*164*4 B
#define B_SMEM (B_T + 64 * B_TSTR * 4)           // 74368

static __device__ __forceinline__ uint32_t smem_u32(const void* p) {
    uint32_t a;
    asm("{ .reg .u64 t; cvta.to.shared.u64 t, %1; cvt.u32.u64 %0, t; }" : "=r"(a) : "l"(p));
    return a;
}
static __device__ __forceinline__ void ldm_x4(uint32_t* r, uint32_t addr) {
    asm volatile("ldmatrix.sync.aligned.m8n8.x4.shared.b16 {%0,%1,%2,%3}, [%4];"
                 : "=r"(r[0]), "=r"(r[1]), "=r"(r[2]), "=r"(r[3]) : "r"(addr));
}
static __device__ __forceinline__ void ldm_x2t(uint32_t* r, uint32_t addr) {
    asm volatile("ldmatrix.sync.aligned.m8n8.x2.trans.shared.b16 {%0,%1}, [%2];"
                 : "=r"(r[0]), "=r"(r[1]) : "r"(addr));
}
static __device__ __forceinline__ void mma_bf16(float* c, const uint32_t* a, const uint32_t* b) {
    asm volatile("mma.sync.aligned.m16n8k16.row.col.f32.bf16.bf16.f32 "
                 "{%0,%1,%2,%3}, {%4,%5,%6,%7}, {%8,%9}, {%0,%1,%2,%3};"
                 : "+f"(c[0]), "+f"(c[1]), "+f"(c[2]), "+f"(c[3])
                 : "r"(a[0]), "r"(a[1]), "r"(a[2]), "r"(a[3]), "r"(b[0]), "r"(b[1]));
}
static __device__ __forceinline__ void split2(float x0, float x1, uint32_t& hi, uint32_t& lo) {
    uint32_t h;
    asm("cvt.rn.bf16x2.f32 %0, %1, %2;" : "=r"(h) : "f"(x1), "f"(x0));
    float h0 = __uint_as_float(h << 16);
    float h1 = __uint_as_float(h & 0xFFFF0000u);
    uint32_t l;
    asm("cvt.rn.bf16x2.f32 %0, %1, %2;" : "=r"(l) : "f"(x1 - h1), "f"(x0 - h0));
    hi = h; lo = l;
}
static __device__ __forceinline__ float* scratch_ptr(int row, int j) {
    if (j < 320) return g_UV + (size_t)row * 320 + j;
    if (j < 448) return g_G1 + (size_t)row * 128 + (j - 320);
    return g_G2 + (size_t)row * 128 + (j - 448);
}

// =====================================================================
// Kernel A (persistent): [NNODE,64] @ BigW[64,576] -> UV | G1 | G2
// =====================================================================
__global__ __launch_bounds__(A_THR, 1)
void node_gemm_kernel(const float* __restrict__ z,
                      const float* __restrict__ Wffw,
                      const float* __restrict__ Wf,
                      const float* __restrict__ Ws)
{
    extern __shared__ char sm[];
    const uint32_t sb = smem_u32(sm);
    const int tid = threadIdx.x, wid = tid >> 5, lane = tid & 31;
    const int mi = wid >> 2, ni = wid & 3;

    for (int idx = tid; idx < 64 * 576; idx += A_THR) {
        const int k = idx / 576, j = idx - k * 576;
        float w;
        if (j < 160)      w = Wffw[k * 160 + j];
        else if (j < 320) w = Wffw[(64 + k) * 160 + (j - 160)];
        else if (j < 384) w = Wf[k * 64 + (j - 320)];
        else if (j < 448) w = Ws[k * 64 + (j - 384)];
        else if (j < 512) w = Wf[(64 + k) * 64 + (j - 448)];
        else              w = Ws[(64 + k) * 64 + (j - 512)];
        const __nv_bfloat16 h = __float2bfloat16(w);
        const __nv_bfloat16 l = __float2bfloat16(w - __bfloat162float(h));
        *reinterpret_cast<__nv_bfloat16*>(sm + A_WH + k * A_WSTR + j * 2) = h;
        *reinterpret_cast<__nv_bfloat16*>(sm + A_WL + k * A_WSTR + j * 2) = l;
    }

    const int r = tid >> 3, cq = (tid & 7) * 8;

    float4 va = make_float4(0.f, 0.f, 0.f, 0.f), vb = va;
    int t = blockIdx.x;
    if (t < A_NT) {
        const int grow = t * A_TILE + r;
        if (grow < NNODE) {
            const float4* zr = reinterpret_cast<const float4*>(z + (size_t)grow * 64 + cq);
            va = zr[0]; vb = zr[1];
        }
    }

    for (; t < A_NT; t += gridDim.x) {
        __syncthreads();

        {
            uint32_t* zh = reinterpret_cast<uint32_t*>(sm + A_ZH + r * A_ZSTR + cq * 2);
            uint32_t* zl = reinterpret_cast<uint32_t*>(sm + A_ZL + r * A_ZSTR + cq * 2);
            uint32_t h0, l0, h1, l1;
            split2(va.x, va.y, h0, l0); split2(va.z, va.w, h1, l1);
            zh[0] = h0; zh[1] = h1; zl[0] = l0; zl[1] = l1;
            split2(vb.x, vb.y, h0, l0); split2(vb.z, vb.w, h1, l1);
            zh[2] = h0; zh[3] = h1; zl[2] = l0; zl[3] = l1;
        }
        __syncthreads();

        const int tn = t + gridDim.x;
        va = make_float4(0.f, 0.f, 0.f, 0.f); vb = va;
        if (tn < A_NT) {
            const int grow = tn * A_TILE + r;
            if (grow < NNODE) {
                const float4* zr = reinterpret_cast<const float4*>(z + (size_t)grow * 64 + cq);
                va = zr[0]; vb = zr[1];
            }
        }

        float acc[18][4];
        #pragma unroll
        for (int n = 0; n < 18; n++)
            #pragma unroll
            for (int q = 0; q < 4; q++) acc[n][q] = 0.0f;

        #pragma unroll
        for (int k = 0; k < 4; k++) {
            uint32_t ah[4], al[4];
            const uint32_t arow = (uint32_t)(mi * 16 + (lane & 15)) * A_ZSTR
                                + (uint32_t)k * 32 + ((lane >> 4) << 4);
            ldm_x4(ah, sb + A_ZH + arow);
            ldm_x4(al, sb + A_ZL + arow);
            const uint32_t brow = (uint32_t)(k * 16 + (lane & 15)) * A_WSTR + (uint32_t)ni * 288;
            #pragma unroll
            for (int n = 0; n < 18; n++) {
                uint32_t bh[2], bl[2];
                ldm_x2t(bh, sb + A_WH + brow + n * 16);
                ldm_x2t(bl, sb + A_WL + brow + n * 16);
                mma_bf16(acc[n], ah, bh);
                mma_bf16(acc[n], al, bh);
                mma_bf16(acc[n], ah, bl);
            }
        }

        const int r0 = t * A_TILE + mi * 16 + (lane >> 2);
        const int r1 = r0 + 8;
        #pragma unroll
        for (int n = 0; n < 18; n++) {
            const int j = ni * 144 + n * 8 + 2 * (lane & 3);
            if (r0 < NNODE) {
                float2 o; o.x = acc[n][0]; o.y = acc[n][1];
                *reinterpret_cast<float2*>(scratch_ptr(r0, j)) = o;
            }
            if (r1 < NNODE) {
                float2 o; o.x = acc[n][2]; o.y = acc[n][3];
                *reinterpret_cast<float2*>(scratch_ptr(r1, j)) = o;
            }
        }
    }
}

// =====================================================================
// Kernel B: z_edge[e] = relu(U[src] + V[dst] + ea[e]@W3 + b)
// U+V staged through SMEM with coalesced 64B quad reads
// =====================================================================
__global__ __launch_bounds__(B_THR, 3)
void edge_assemble_kernel(const float* __restrict__ ea,
                          const int*   __restrict__ srcp,
                          const int*   __restrict__ dstp,
                          const float* __restrict__ Wffw,
                          const float* __restrict__ bias,
                          float* __restrict__ z_edge)
{
    extern __shared__ char sm[];
    const uint32_t sb = smem_u32(sm);
    const int tid = threadIdx.x, wid = tid >> 5, lane = tid & 31;
    const int mi = wid >> 2, ni = wid & 3;

    for (int idx = tid; idx < 32 * 160; idx += B_THR) {
        const int k = idx / 160, n = idx - k * 160;
        const float w = Wffw[(128 + k) * 160 + n];
        const __nv_bfloat16 h = __float2bfloat16(w);
        const __nv_bfloat16 l = __float2bfloat16(w - __bfloat162float(h));
        *reinterpret_cast<__nv_bfloat16*>(sm + B_WH + k * B_WSTR + n * 2) = h;
        *reinterpret_cast<__nv_bfloat16*>(sm + B_WL + k * B_WSTR + n * 2) = l;
    }
    if (tid < 160) reinterpret_cast<float*>(sm + B_BIAS)[tid] = bias[tid];
    const float* s_bias = reinterpret_cast<const float*>(sm + B_BIAS);

    const int e_loc = tid >> 2, q = tid & 3;

    for (int t = blockIdx.x; t < B_NT; t += gridDim.x) {
        __syncthreads();

        const int ge = t * B_TILE + e_loc;
        // ---- ea tile (bf16 hi/lo) ----
        {
            const float4* ep = reinterpret_cast<const float4*>(ea + (size_t)ge * 32) + q * 2;
            const float4 a = ep[0], b = ep[1];
            uint32_t* xh = reinterpret_cast<uint32_t*>(sm + B_EH + e_loc * B_ESTR + q * 16);
            uint32_t* xl = reinterpret_cast<uint32_t*>(sm + B_EL + e_loc * B_ESTR + q * 16);
            uint32_t h0, l0, h1, l1;
            split2(a.x, a.y, h0, l0); split2(a.z, a.w, h1, l1);
            xh[0] = h0; xh[1] = h1; xl[0] = l0; xl[1] = l1;
            split2(b.x, b.y, h0, l0); split2(b.z, b.w, h1, l1);
            xh[2] = h0; xh[3] = h1; xl[2] = l0; xl[3] = l1;
        }
        // ---- T = U[src] + V[dst], coalesced (quad covers 64B per step) ----
        {
            const int s = srcp[ge], d = dstp[ge];
            const float4* Ur = reinterpret_cast<const float4*>(g_UV + (size_t)s * 320);
            const float4* Vr = reinterpret_cast<const float4*>(g_UV + (size_t)d * 320 + 160);
            float* Trow = reinterpret_cast<float*>(sm + B_T) + e_loc * B_TSTR;
            #pragma unroll
            for (int i = 0; i < 10; i++) {
                const int f4 = q + 4 * i;            // 0..39, quad-contiguous
                const float4 u = Ur[f4], v = Vr[f4];
                float4 w;
                w.x = u.x + v.x; w.y = u.y + v.y; w.z = u.z + v.z; w.w = u.w + v.w;
                *reinterpret_cast<float4*>(Trow + 4 * f4) = w;
            }
        }
        __syncthreads();

        // ---- small GEMM ea@W3: K=32 ----
        float acc[2][5][4];
        #pragma unroll
        for (int m = 0; m < 2; m++)
            #pragma unroll
            for (int n = 0; n < 5; n++)
                #pragma unroll
                for (int r = 0; r < 4; r++) acc[m][n][r] = 0.0f;

        #pragma unroll
        for (int k = 0; k < 2; k++) {
            uint32_t ah[2][4], al[2][4];
            const uint32_t arow = (uint32_t)(mi * 32 + (lane & 15)) * B_ESTR
                                + (uint32_t)k * 32 + ((lane >> 4) << 4);
            #pragma unroll
            for (int m = 0; m < 2; m++) {
                ldm_x4(ah[m], sb + B_EH + arow + m * 16 * B_ESTR);
                ldm_x4(al[m], sb + B_EL + arow + m * 16 * B_ESTR);
            }
            const uint32_t brow = (uint32_t)(k * 16 + (lane & 15)) * B_WSTR + (uint32_t)ni * 80;
            #pragma unroll
            for (int n = 0; n < 5; n++) {
                uint32_t bh[2], bl[2];
                ldm_x2t(bh, sb + B_WH + brow + n * 16);
                ldm_x2t(bl, sb + B_WL + brow + n * 16);
                #pragma unroll
                for (int m = 0; m < 2; m++) {
                    mma_bf16(acc[m][n], ah[m], bh);
                    mma_bf16(acc[m][n], al[m], bh);
                    mma_bf16(acc[m][n], ah[m], bl);
                }
            }
        }

        // ---- epilogue: + T(smem) + bias, relu, store ----
        #pragma unroll
        for (int m = 0; m < 2; m++) {
            const int le0 = mi * 32 + m * 16 + (lane >> 2);
            const int r0 = t * B_TILE + le0;
            const float* T0 = reinterpret_cast<const float*>(sm + B_T) + le0 * B_TSTR;
            const float* T1 = T0 + 8 * B_TSTR;
            #pragma unroll
            for (int n = 0; n < 5; n++) {
                const int j = ni * 40 + n * 8 + 2 * (lane & 3);
                const float2 t0 = *reinterpret_cast<const float2*>(T0 + j);
                const float2 t1 = *reinterpret_cast<const float2*>(T1 + j);
                const float b0 = s_bias[j], b1 = s_bias[j + 1];
                float2 o0, o1;
                o0.x = fmaxf(acc[m][n][0] + t0.x + b0, 0.0f);
                o0.y = fmaxf(acc[m][n][1] + t0.y + b1, 0.0f);
                o1.x = fmaxf(acc[m][n][2] + t1.x + b0, 0.0f);
                o1.y = fmaxf(acc[m][n][3] + t1.y + b1, 0.0f);
                *reinterpret_cast<float2*>(z_edge + (size_t)r0 * 160 + j) = o0;
                *reinterpret_cast<float2*>(z_edge + (size_t)(r0 + 8) * 160 + j) = o1;
            }
        }
    }
}

// =====================================================================
// Kernel C: msg = sigmoid(P[dst]+Q[src]+bf) * softplus(R[dst]+S[src]+bs)
//           z_node[dst] += msg    (quad covers contiguous 64B per step)
// =====================================================================
static __device__ __forceinline__ float lut_eval(const float2* tab, float x) {
    float tp = fmaf(x, 512.0f / 20.0f, 256.0f);
    tp = fminf(fmaxf(tp, 0.0f), 511.5f);
    const float2 c = tab[(int)tp];
    return fmaf(tp, c.y, c.x);
}

__global__ __launch_bounds__(256)
void gate_assemble_kernel(const int* __restrict__ srcp,
                          const int* __restrict__ dstp,
                          const float* __restrict__ bf,
                          const float* __restrict__ bs,
                          float* __restrict__ z_node)
{
    __shared__ float2 t_sig[512];
    __shared__ float2 t_sp[512];
    __shared__ float s_bf[64], s_bs[64];

    const int tid = threadIdx.x;
    for (int i = tid; i < 512; i += 256) {
        const float x0 = -10.0f + (float)i * (20.0f / 512.0f);
        const float x1 = x0 + (20.0f / 512.0f);
        const float s0 = 1.0f / (1.0f + expf(-x0));
        const float s1 = 1.0f / (1.0f + expf(-x1));
        const float ds = s1 - s0;
        t_sig[i] = make_float2(s0 - (float)i * ds, ds);
        const float p0 = fmaxf(x0, 0.0f) + log1pf(expf(-fabsf(x0)));
        const float p1 = fmaxf(x1, 0.0f) + log1pf(expf(-fabsf(x1)));
        const float dp = p1 - p0;
        t_sp[i] = make_float2(p0 - (float)i * dp, dp);
    }
    if (tid < 64) { s_bf[tid] = bf[tid]; s_bs[tid] = bs[tid]; }
    __syncthreads();

    const int e = blockIdx.x * 64 + (tid >> 2);
    const int q = tid & 3;
    const int d = dstp[e], s = srcp[e];
    const float4* Pf = reinterpret_cast<const float4*>(g_G1 + (size_t)d * 128) + q;
    const float4* Qf = reinterpret_cast<const float4*>(g_G2 + (size_t)s * 128) + q;
    const float4* Ps = reinterpret_cast<const float4*>(g_G1 + (size_t)d * 128 + 64) + q;
    const float4* Qs = reinterpret_cast<const float4*>(g_G2 + (size_t)s * 128 + 64) + q;
    float* out = z_node + (size_t)d * 64 + q * 4;

    #pragma unroll
    for (int j = 0; j < 4; j++) {
        const float4 pf = Pf[4 * j], qf = Qf[4 * j], ps = Ps[4 * j], qs = Qs[4 * j];
        const int c = q * 4 + 16 * j;
        float4 msg;
        {
            const float f = pf.x + qf.x + s_bf[c + 0];
            const float v = ps.x + qs.x + s_bs[c + 0];
            msg.x = lut_eval(t_sig, f) * fmaxf(lut_eval(t_sp, v), v);
        }
        {
            const float f = pf.y + qf.y + s_bf[c + 1];
            const float v = ps.y + qs.y + s_bs[c + 1];
            msg.y = lut_eval(t_sig, f) * fmaxf(lut_eval(t_sp, v), v);
        }
        {
            const float f = pf.z + qf.z + s_bf[c + 2];
            const float v = ps.z + qs.z + s_bs[c + 2];
            msg.z = lut_eval(t_sig, f) * fmaxf(lut_eval(t_sp, v), v);
        }
        {
            const float f = pf.w + qf.w + s_bf[c + 3];
            const float v = ps.w + qs.w + s_bs[c + 3];
            msg.w = lut_eval(t_sig, f) * fmaxf(lut_eval(t_sp, v), v);
        }
        atomicAdd(reinterpret_cast<float4*>(out + 16 * j), msg);
    }
}

extern "C" void kernel_launch(void* const* d_in, const int* in_sizes, int n_in,
                              void* d_out, int out_size)
{
    const float* z    = (const float*)d_in[0];
    const float* ea   = (const float*)d_in[1];
    const int*   eidx = (const int*)  d_in[2];
    const float* Wffw = (const float*)d_in[3];
    const float* bffw = (const float*)d_in[4];
    const float* Wf   = (const float*)d_in[5];
    const float* bf   = (const float*)d_in[6];
    const float* Ws   = (const float*)d_in[7];
    const float* bs   = (const float*)d_in[8];

    float* z_node = (float*)d_out;
    float* z_edge = (float*)d_out + (size_t)NNODE * 64;
    const int* srcp = eidx;
    const int* dstp = eidx + NE;

    static cudaStream_t s2 = nullptr;
    static cudaEvent_t evA = nullptr, evC = nullptr;
    if (s2 == nullptr) {
        cudaStreamCreateWithFlags(&s2, cudaStreamNonBlocking);
        cudaEventCreateWithFlags(&evA, cudaEventDisableTiming);
        cudaEventCreateWithFlags(&evC, cudaEventDisableTiming);
        cudaFuncSetAttribute(node_gemm_kernel, cudaFuncAttributeMaxDynamicSharedMemorySize, A_SMEM);
        cudaFuncSetAttribute(edge_assemble_kernel, cudaFuncAttributeMaxDynamicSharedMemorySize, B_SMEM);
    }

    cudaMemcpyAsync(z_node, z, (size_t)NNODE * 64 * sizeof(float),
                    cudaMemcpyDeviceToDevice, 0);
    node_gemm_kernel<<<148, A_THR, A_SMEM, 0>>>(z, Wffw, Wf, Ws);
    cudaEventRecord(evA, 0);

    cudaStreamWaitEvent(s2, evA, 0);
    gate_assemble_kernel<<<B_NT, 256, 0, s2>>>(srcp, dstp, bf, bs, z_node);
    cudaEventRecord(evC, s2);

    edge_assemble_kernel<<<444, B_THR, B_SMEM, 0>>>(ea, srcp, dstp, Wffw, bffw, z_edge);

    cudaStreamWaitEvent(0, evC, 0);
}

// round 10
// speedup vs baseline: 1.5499x; 1.5499x over previous
#include <cuda_runtime.h>
#include <cuda_bf16.h>
#include <cstdint>
#include <math.h>

#define NE      800000
#define NNODE   50000

// ---------------- scratch (static device arrays; no allocation) ----------------
__device__ float g_UV[(size_t)NNODE * 320];   // [n][0:160]=U=z@W1, [160:320]=V=z@W2
__device__ float g_G1[(size_t)NNODE * 128];   // [n][0:64]=P=z@Wf_top, [64:128]=R=z@Ws_top
__device__ float g_G2[(size_t)NNODE * 128];   // [n][0:64]=Q=z@Wf_bot, [64:128]=S=z@Ws_bot

// ---------------- kernel A (node GEMM, persistent) ----------------
#define A_THR  512
#define A_TILE 64
#define A_NT   ((NNODE + A_TILE - 1) / A_TILE)   // 782
#define A_ZSTR 144
#define A_WSTR 1168
#define A_ZH   0
#define A_ZL   (A_ZH + 64 * A_ZSTR)
#define A_WH   (A_ZL + 64 * A_ZSTR)
#define A_WL   (A_WH + 64 * A_WSTR)
#define A_SMEM (A_WL + 64 * A_WSTR)              // 167936

// ---------------- kernel B (edge assemble + ea@W3) ----------------
#define B_THR  256
#define B_TILE 64
#define B_NT   (NE / B_TILE)                     // 12500
#define B_ESTR 80
#define B_WSTR 336
#define B_EH   0
#define B_EL   (B_EH + 64 * B_ESTR)
#define B_WH   (B_EL + 64 * B_ESTR)
#define B_WL   (B_WH + 32 * B_WSTR)
#define B_BIAS (B_WL + 32 * B_WSTR)
#define B_SMEM (B_BIAS + 640)                    // 32384

static __device__ __forceinline__ uint32_t smem_u32(const void* p) {
    uint32_t a;
    asm("{ .reg .u64 t; cvta.to.shared.u64 t, %1; cvt.u32.u64 %0, t; }" : "=r"(a) : "l"(p));
    return a;
}
static __device__ __forceinline__ void ldm_x4(uint32_t* r, uint32_t addr) {
    asm volatile("ldmatrix.sync.aligned.m8n8.x4.shared.b16 {%0,%1,%2,%3}, [%4];"
                 : "=r"(r[0]), "=r"(r[1]), "=r"(r[2]), "=r"(r[3]) : "r"(addr));
}
static __device__ __forceinline__ void ldm_x2t(uint32_t* r, uint32_t addr) {
    asm volatile("ldmatrix.sync.aligned.m8n8.x2.trans.shared.b16 {%0,%1}, [%2];"
                 : "=r"(r[0]), "=r"(r[1]) : "r"(addr));
}
static __device__ __forceinline__ void mma_bf16(float* c, const uint32_t* a, const uint32_t* b) {
    asm volatile("mma.sync.aligned.m16n8k16.row.col.f32.bf16.bf16.f32 "
                 "{%0,%1,%2,%3}, {%4,%5,%6,%7}, {%8,%9}, {%0,%1,%2,%3};"
                 : "+f"(c[0]), "+f"(c[1]), "+f"(c[2]), "+f"(c[3])
                 : "r"(a[0]), "r"(a[1]), "r"(a[2]), "r"(a[3]), "r"(b[0]), "r"(b[1]));
}
static __device__ __forceinline__ void split2(float x0, float x1, uint32_t& hi, uint32_t& lo) {
    uint32_t h;
    asm("cvt.rn.bf16x2.f32 %0, %1, %2;" : "=r"(h) : "f"(x1), "f"(x0));
    float h0 = __uint_as_float(h << 16);
    float h1 = __uint_as_float(h & 0xFFFF0000u);
    uint32_t l;
    asm("cvt.rn.bf16x2.f32 %0, %1, %2;" : "=r"(l) : "f"(x1 - h1), "f"(x0 - h0));
    hi = h; lo = l;
}
static __device__ __forceinline__ float* scratch_ptr(int row, int j) {
    if (j < 320) return g_UV + (size_t)row * 320 + j;
    if (j < 448) return g_G1 + (size_t)row * 128 + (j - 320);
    return g_G2 + (size_t)row * 128 + (j - 448);
}

// =====================================================================
// Kernel A (persistent): [NNODE,64] @ BigW[64,576] -> UV | G1 | G2
// =====================================================================
__global__ __launch_bounds__(A_THR, 1)
void node_gemm_kernel(const float* __restrict__ z,
                      const float* __restrict__ Wffw,
                      const float* __restrict__ Wf,
                      const float* __restrict__ Ws)
{
    extern __shared__ char sm[];
    const uint32_t sb = smem_u32(sm);
    const int tid = threadIdx.x, wid = tid >> 5, lane = tid & 31;
    const int mi = wid >> 2, ni = wid & 3;

    for (int idx = tid; idx < 64 * 576; idx += A_THR) {
        const int k = idx / 576, j = idx - k * 576;
        float w;
        if (j < 160)      w = Wffw[k * 160 + j];
        else if (j < 320) w = Wffw[(64 + k) * 160 + (j - 160)];
        else if (j < 384) w = Wf[k * 64 + (j - 320)];
        else if (j < 448) w = Ws[k * 64 + (j - 384)];
        else if (j < 512) w = Wf[(64 + k) * 64 + (j - 448)];
        else              w = Ws[(64 + k) * 64 + (j - 512)];
        const __nv_bfloat16 h = __float2bfloat16(w);
        const __nv_bfloat16 l = __float2bfloat16(w - __bfloat162float(h));
        *reinterpret_cast<__nv_bfloat16*>(sm + A_WH + k * A_WSTR + j * 2) = h;
        *reinterpret_cast<__nv_bfloat16*>(sm + A_WL + k * A_WSTR + j * 2) = l;
    }

    const int r = tid >> 3, cq = (tid & 7) * 8;

    float4 va = make_float4(0.f, 0.f, 0.f, 0.f), vb = va;
    int t = blockIdx.x;
    if (t < A_NT) {
        const int grow = t * A_TILE + r;
        if (grow < NNODE) {
            const float4* zr = reinterpret_cast<const float4*>(z + (size_t)grow * 64 + cq);
            va = zr[0]; vb = zr[1];
        }
    }

    for (; t < A_NT; t += gridDim.x) {
        __syncthreads();

        {
            uint32_t* zh = reinterpret_cast<uint32_t*>(sm + A_ZH + r * A_ZSTR + cq * 2);
            uint32_t* zl = reinterpret_cast<uint32_t*>(sm + A_ZL + r * A_ZSTR + cq * 2);
            uint32_t h0, l0, h1, l1;
            split2(va.x, va.y, h0, l0); split2(va.z, va.w, h1, l1);
            zh[0] = h0; zh[1] = h1; zl[0] = l0; zl[1] = l1;
            split2(vb.x, vb.y, h0, l0); split2(vb.z, vb.w, h1, l1);
            zh[2] = h0; zh[3] = h1; zl[2] = l0; zl[3] = l1;
        }
        __syncthreads();

        const int tn = t + gridDim.x;
        va = make_float4(0.f, 0.f, 0.f, 0.f); vb = va;
        if (tn < A_NT) {
            const int grow = tn * A_TILE + r;
            if (grow < NNODE) {
                const float4* zr = reinterpret_cast<const float4*>(z + (size_t)grow * 64 + cq);
                va = zr[0]; vb = zr[1];
            }
        }

        float acc[18][4];
        #pragma unroll
        for (int n = 0; n < 18; n++)
            #pragma unroll
            for (int q = 0; q < 4; q++) acc[n][q] = 0.0f;

        #pragma unroll
        for (int k = 0; k < 4; k++) {
            uint32_t ah[4], al[4];
            const uint32_t arow = (uint32_t)(mi * 16 + (lane & 15)) * A_ZSTR
                                + (uint32_t)k * 32 + ((lane >> 4) << 4);
            ldm_x4(ah, sb + A_ZH + arow);
            ldm_x4(al, sb + A_ZL + arow);
            const uint32_t brow = (uint32_t)(k * 16 + (lane & 15)) * A_WSTR + (uint32_t)ni * 288;
            #pragma unroll
            for (int n = 0; n < 18; n++) {
                uint32_t bh[2], bl[2];
                ldm_x2t(bh, sb + A_WH + brow + n * 16);
                ldm_x2t(bl, sb + A_WL + brow + n * 16);
                mma_bf16(acc[n], ah, bh);
                mma_bf16(acc[n], al, bh);
                mma_bf16(acc[n], ah, bl);
            }
        }

        const int r0 = t * A_TILE + mi * 16 + (lane >> 2);
        const int r1 = r0 + 8;
        #pragma unroll
        for (int n = 0; n < 18; n++) {
            const int j = ni * 144 + n * 8 + 2 * (lane & 3);
            if (r0 < NNODE) {
                float2 o; o.x = acc[n][0]; o.y = acc[n][1];
                *reinterpret_cast<float2*>(scratch_ptr(r0, j)) = o;
            }
            if (r1 < NNODE) {
                float2 o; o.x = acc[n][2]; o.y = acc[n][3];
                *reinterpret_cast<float2*>(scratch_ptr(r1, j)) = o;
            }
        }
    }
}

// =====================================================================
// Kernel B: z_edge[e] = relu(U[src] + V[dst] + ea[e]@W3 + b)
// epilogue: U/V loads front-batched per m-half (MLP 20)
// =====================================================================
__global__ __launch_bounds__(B_THR, 3)
void edge_assemble_kernel(const float* __restrict__ ea,
                          const int*   __restrict__ srcp,
                          const int*   __restrict__ dstp,
                          const float* __restrict__ Wffw,
                          const float* __restrict__ bias,
                          float* __restrict__ z_edge)
{
    extern __shared__ char sm[];
    const uint32_t sb = smem_u32(sm);
    const int tid = threadIdx.x, wid = tid >> 5, lane = tid & 31;
    const int mi = wid >> 2, ni = wid & 3;

    for (int idx = tid; idx < 32 * 160; idx += B_THR) {
        const int k = idx / 160, n = idx - k * 160;
        const float w = Wffw[(128 + k) * 160 + n];
        const __nv_bfloat16 h = __float2bfloat16(w);
        const __nv_bfloat16 l = __float2bfloat16(w - __bfloat162float(h));
        *reinterpret_cast<__nv_bfloat16*>(sm + B_WH + k * B_WSTR + n * 2) = h;
        *reinterpret_cast<__nv_bfloat16*>(sm + B_WL + k * B_WSTR + n * 2) = l;
    }
    if (tid < 160) reinterpret_cast<float*>(sm + B_BIAS)[tid] = bias[tid];
    const float* s_bias = reinterpret_cast<const float*>(sm + B_BIAS);

    for (int t = blockIdx.x; t < B_NT; t += gridDim.x) {
        __syncthreads();

        {
            const int e_loc = tid >> 2, q = tid & 3;
            const int ge = t * B_TILE + e_loc;
            const float4* ep = reinterpret_cast<const float4*>(ea + (size_t)ge * 32) + q * 2;
            const float4 a = ep[0], b = ep[1];
            uint32_t* xh = reinterpret_cast<uint32_t*>(sm + B_EH + e_loc * B_ESTR + q * 16);
            uint32_t* xl = reinterpret_cast<uint32_t*>(sm + B_EL + e_loc * B_ESTR + q * 16);
            uint32_t h0, l0, h1, l1;
            split2(a.x, a.y, h0, l0); split2(a.z, a.w, h1, l1);
            xh[0] = h0; xh[1] = h1; xl[0] = l0; xl[1] = l1;
            split2(b.x, b.y, h0, l0); split2(b.z, b.w, h1, l1);
            xh[2] = h0; xh[3] = h1; xl[2] = l0; xl[3] = l1;
        }
        __syncthreads();

        float acc[2][5][4];
        #pragma unroll
        for (int m = 0; m < 2; m++)
            #pragma unroll
            for (int n = 0; n < 5; n++)
                #pragma unroll
                for (int r = 0; r < 4; r++) acc[m][n][r] = 0.0f;

        #pragma unroll
        for (int k = 0; k < 2; k++) {
            uint32_t ah[2][4], al[2][4];
            const uint32_t arow = (uint32_t)(mi * 32 + (lane & 15)) * B_ESTR
                                + (uint32_t)k * 32 + ((lane >> 4) << 4);
            #pragma unroll
            for (int m = 0; m < 2; m++) {
                ldm_x4(ah[m], sb + B_EH + arow + m * 16 * B_ESTR);
                ldm_x4(al[m], sb + B_EL + arow + m * 16 * B_ESTR);
            }
            const uint32_t brow = (uint32_t)(k * 16 + (lane & 15)) * B_WSTR + (uint32_t)ni * 80;
            #pragma unroll
            for (int n = 0; n < 5; n++) {
                uint32_t bh[2], bl[2];
                ldm_x2t(bh, sb + B_WH + brow + n * 16);
                ldm_x2t(bl, sb + B_WL + brow + n * 16);
                #pragma unroll
                for (int m = 0; m < 2; m++) {
                    mma_bf16(acc[m][n], ah[m], bh);
                    mma_bf16(acc[m][n], al[m], bh);
                    mma_bf16(acc[m][n], ah[m], bl);
                }
            }
        }

        // ---- epilogue: front-batched U/V gather, then bias+relu+store ----
        #pragma unroll
        for (int m = 0; m < 2; m++) {
            const int r0 = t * B_TILE + mi * 32 + m * 16 + (lane >> 2);
            const int r1 = r0 + 8;
            const int s0 = srcp[r0], d0 = dstp[r0];
            const int s1 = srcp[r1], d1 = dstp[r1];
            const float* U0 = g_UV + (size_t)s0 * 320;
            const float* V0 = g_UV + (size_t)d0 * 320 + 160;
            const float* U1 = g_UV + (size_t)s1 * 320;
            const float* V1 = g_UV + (size_t)d1 * 320 + 160;
            const int jb = ni * 40 + 2 * (lane & 3);

            float2 t0[5], t1[5];
            #pragma unroll
            for (int n = 0; n < 5; n++) {
                const int j = jb + n * 8;
                const float2 u0 = *reinterpret_cast<const float2*>(U0 + j);
                const float2 v0 = *reinterpret_cast<const float2*>(V0 + j);
                const float2 u1 = *reinterpret_cast<const float2*>(U1 + j);
                const float2 v1 = *reinterpret_cast<const float2*>(V1 + j);
                t0[n].x = u0.x + v0.x; t0[n].y = u0.y + v0.y;
                t1[n].x = u1.x + v1.x; t1[n].y = u1.y + v1.y;
            }
            #pragma unroll
            for (int n = 0; n < 5; n++) {
                const int j = jb + n * 8;
                const float b0 = s_bias[j], b1 = s_bias[j + 1];
                float2 o0, o1;
                o0.x = fmaxf(acc[m][n][0] + t0[n].x + b0, 0.0f);
                o0.y = fmaxf(acc[m][n][1] + t0[n].y + b1, 0.0f);
                o1.x = fmaxf(acc[m][n][2] + t1[n].x + b0, 0.0f);
                o1.y = fmaxf(acc[m][n][3] + t1[n].y + b1, 0.0f);
                *reinterpret_cast<float2*>(z_edge + (size_t)r0 * 160 + j) = o0;
                *reinterpret_cast<float2*>(z_edge + (size_t)r1 * 160 + j) = o1;
            }
        }
    }
}

// =====================================================================
// Kernel C: msg = sigmoid(P[dst]+Q[src]+bf) * softplus(R[dst]+S[src]+bs)
//           z_node[dst] += msg     (all 16 gathers front-batched)
// =====================================================================
static __device__ __forceinline__ float lut_eval(const float2* tab, float x) {
    float tp = fmaf(x, 512.0f / 20.0f, 256.0f);
    tp = fminf(fmaxf(tp, 0.0f), 511.5f);
    const float2 c = tab[(int)tp];
    return fmaf(tp, c.y, c.x);
}

__global__ __launch_bounds__(256)
void gate_assemble_kernel(const int* __restrict__ srcp,
                          const int* __restrict__ dstp,
                          const float* __restrict__ bf,
                          const float* __restrict__ bs,
                          float* __restrict__ z_node)
{
    __shared__ float2 t_sig[512];
    __shared__ float2 t_sp[512];
    __shared__ float s_bf[64], s_bs[64];

    const int tid = threadIdx.x;
    for (int i = tid; i < 512; i += 256) {
        const float x0 = -10.0f + (float)i * (20.0f / 512.0f);
        const float x1 = x0 + (20.0f / 512.0f);
        const float s0 = 1.0f / (1.0f + expf(-x0));
        const float s1 = 1.0f / (1.0f + expf(-x1));
        const float ds = s1 - s0;
        t_sig[i] = make_float2(s0 - (float)i * ds, ds);
        const float p0 = fmaxf(x0, 0.0f) + log1pf(expf(-fabsf(x0)));
        const float p1 = fmaxf(x1, 0.0f) + log1pf(expf(-fabsf(x1)));
        const float dp = p1 - p0;
        t_sp[i] = make_float2(p0 - (float)i * dp, dp);
    }
    if (tid < 64) { s_bf[tid] = bf[tid]; s_bs[tid] = bs[tid]; }
    __syncthreads();

    const int e = blockIdx.x * 64 + (tid >> 2);
    const int c0 = (tid & 3) * 16;
    const int d = dstp[e], s = srcp[e];
    const float4* Pf = reinterpret_cast<const float4*>(g_G1 + (size_t)d * 128 + c0);
    const float4* Qf = reinterpret_cast<const float4*>(g_G2 + (size_t)s * 128 + c0);
    const float4* Ps = reinterpret_cast<const float4*>(g_G1 + (size_t)d * 128 + 64 + c0);
    const float4* Qs = reinterpret_cast<const float4*>(g_G2 + (size_t)s * 128 + 64 + c0);
    float* out = z_node + (size_t)d * 64 + c0;

    // front-batch ALL 16 gathers (MLP 16)
    float4 pf[4], qf[4], ps[4], qs[4];
    #pragma unroll
    for (int j = 0; j < 4; j++) pf[j] = Pf[j];
    #pragma unroll
    for (int j = 0; j < 4; j++) qf[j] = Qf[j];
    #pragma unroll
    for (int j = 0; j < 4; j++) ps[j] = Ps[j];
    #pragma unroll
    for (int j = 0; j < 4; j++) qs[j] = Qs[j];

    #pragma unroll
    for (int j = 0; j < 4; j++) {
        const int c = c0 + 4 * j;
        float4 msg;
        {
            const float f = pf[j].x + qf[j].x + s_bf[c + 0];
            const float v = ps[j].x + qs[j].x + s_bs[c + 0];
            msg.x = lut_eval(t_sig, f) * fmaxf(lut_eval(t_sp, v), v);
        }
        {
            const float f = pf[j].y + qf[j].y + s_bf[c + 1];
            const float v = ps[j].y + qs[j].y + s_bs[c + 1];
            msg.y = lut_eval(t_sig, f) * fmaxf(lut_eval(t_sp, v), v);
        }
        {
            const float f = pf[j].z + qf[j].z + s_bf[c + 2];
            const float v = ps[j].z + qs[j].z + s_bs[c + 2];
            msg.z = lut_eval(t_sig, f) * fmaxf(lut_eval(t_sp, v), v);
        }
        {
            const float f = pf[j].w + qf[j].w + s_bf[c + 3];
            const float v = ps[j].w + qs[j].w + s_bs[c + 3];
            msg.w = lut_eval(t_sig, f) * fmaxf(lut_eval(t_sp, v), v);
        }
        atomicAdd(reinterpret_cast<float4*>(out + 4 * j), msg);
    }
}

extern "C" void kernel_launch(void* const* d_in, const int* in_sizes, int n_in,
                              void* d_out, int out_size)
{
    const float* z    = (const float*)d_in[0];
    const float* ea   = (const float*)d_in[1];
    const int*   eidx = (const int*)  d_in[2];
    const float* Wffw = (const float*)d_in[3];
    const float* bffw = (const float*)d_in[4];
    const float* Wf   = (const float*)d_in[5];
    const float* bf   = (const float*)d_in[6];
    const float* Ws   = (const float*)d_in[7];
    const float* bs   = (const float*)d_in[8];

    float* z_node = (float*)d_out;
    float* z_edge = (float*)d_out + (size_t)NNODE * 64;
    const int* srcp = eidx;
    const int* dstp = eidx + NE;

    static cudaStream_t s2 = nullptr;
    static cudaEvent_t evA = nullptr, evC = nullptr;
    if (s2 == nullptr) {
        cudaStreamCreateWithFlags(&s2, cudaStreamNonBlocking);
        cudaEventCreateWithFlags(&evA, cudaEventDisableTiming);
        cudaEventCreateWithFlags(&evC, cudaEventDisableTiming);
        cudaFuncSetAttribute(node_gemm_kernel, cudaFuncAttributeMaxDynamicSharedMemorySize, A_SMEM);
        cudaFuncSetAttribute(edge_assemble_kernel, cudaFuncAttributeMaxDynamicSharedMemorySize, B_SMEM);
    }

    cudaMemcpyAsync(z_node, z, (size_t)NNODE * 64 * sizeof(float),
                    cudaMemcpyDeviceToDevice, 0);
    node_gemm_kernel<<<148, A_THR, A_SMEM, 0>>>(z, Wffw, Wf, Ws);
    cudaEventRecord(evA, 0);

    cudaStreamWaitEvent(s2, evA, 0);
    gate_assemble_kernel<<<B_NT, 256, 0, s2>>>(srcp, dstp, bf, bs, z_node);
    cudaEventRecord(evC, s2);

    edge_assemble_kernel<<<444, B_THR, B_SMEM, 0>>>(ea, srcp, dstp, Wffw, bffw, z_edge);

    cudaStreamWaitEvent(0, evC, 0);
}

// round 11
// speedup vs baseline: 1.5731x; 1.0149x over previous
#include <cuda_runtime.h>
#include <cuda_bf16.h>
#include <cstdint>
#include <math.h>

#define NE      800000
#define NNODE   50000

// ---------------- scratch (static device arrays; no allocation) ----------------
__device__ float g_UV[(size_t)NNODE * 320];   // [n][0:160]=U=z@W1, [160:320]=V=z@W2
__device__ float g_G1[(size_t)NNODE * 128];   // [n][0:64]=P=z@Wf_top, [64:128]=R=z@Ws_top
__device__ float g_G2[(size_t)NNODE * 128];   // [n][0:64]=Q=z@Wf_bot, [64:128]=S=z@Ws_bot

// ---------------- kernel A (node GEMM, persistent) ----------------
#define A_THR  512
#define A_TILE 64
#define A_NT   ((NNODE + A_TILE - 1) / A_TILE)   // 782
#define A_ZSTR 144
#define A_WSTR 1168
#define A_ZH   0
#define A_ZL   (A_ZH + 64 * A_ZSTR)
#define A_WH   (A_ZL + 64 * A_ZSTR)
#define A_WL   (A_WH + 64 * A_WSTR)
#define A_SMEM (A_WL + 64 * A_WSTR)              // 167936

// ---------------- kernel F (fused edge assemble + gate) ----------------
#define F_THR  256
#define F_TILE 64
#define F_NT   (NE / F_TILE)                     // 12500
#define F_ESTR 80
#define F_WSTR 336
#define F_EH   0
#define F_EL   (F_EH + 64 * F_ESTR)
#define F_WH   (F_EL + 64 * F_ESTR)
#define F_WL   (F_WH + 32 * F_WSTR)
#define F_BIAS (F_WL + 32 * F_WSTR)
#define F_LSIG (F_BIAS + 640)
#define F_LSP  (F_LSIG + 4096)
#define F_BF   (F_LSP + 4096)
#define F_BS   (F_BF + 256)
#define F_SMEM (F_BS + 256)                      // 41088  (3 CTAs/SM)

static __device__ __forceinline__ uint32_t smem_u32(const void* p) {
    uint32_t a;
    asm("{ .reg .u64 t; cvta.to.shared.u64 t, %1; cvt.u32.u64 %0, t; }" : "=r"(a) : "l"(p));
    return a;
}
static __device__ __forceinline__ void ldm_x4(uint32_t* r, uint32_t addr) {
    asm volatile("ldmatrix.sync.aligned.m8n8.x4.shared.b16 {%0,%1,%2,%3}, [%4];"
                 : "=r"(r[0]), "=r"(r[1]), "=r"(r[2]), "=r"(r[3]) : "r"(addr));
}
static __device__ __forceinline__ void ldm_x2t(uint32_t* r, uint32_t addr) {
    asm volatile("ldmatrix.sync.aligned.m8n8.x2.trans.shared.b16 {%0,%1}, [%2];"
                 : "=r"(r[0]), "=r"(r[1]) : "r"(addr));
}
static __device__ __forceinline__ void mma_bf16(float* c, const uint32_t* a, const uint32_t* b) {
    asm volatile("mma.sync.aligned.m16n8k16.row.col.f32.bf16.bf16.f32 "
                 "{%0,%1,%2,%3}, {%4,%5,%6,%7}, {%8,%9}, {%0,%1,%2,%3};"
                 : "+f"(c[0]), "+f"(c[1]), "+f"(c[2]), "+f"(c[3])
                 : "r"(a[0]), "r"(a[1]), "r"(a[2]), "r"(a[3]), "r"(b[0]), "r"(b[1]));
}
static __device__ __forceinline__ void split2(float x0, float x1, uint32_t& hi, uint32_t& lo) {
    uint32_t h;
    asm("cvt.rn.bf16x2.f32 %0, %1, %2;" : "=r"(h) : "f"(x1), "f"(x0));
    float h0 = __uint_as_float(h << 16);
    float h1 = __uint_as_float(h & 0xFFFF0000u);
    uint32_t l;
    asm("cvt.rn.bf16x2.f32 %0, %1, %2;" : "=r"(l) : "f"(x1 - h1), "f"(x0 - h0));
    hi = h; lo = l;
}
static __device__ __forceinline__ float* scratch_ptr(int row, int j) {
    if (j < 320) return g_UV + (size_t)row * 320 + j;
    if (j < 448) return g_G1 + (size_t)row * 128 + (j - 320);
    return g_G2 + (size_t)row * 128 + (j - 448);
}
static __device__ __forceinline__ float lut_eval(const float2* tab, float x) {
    float tp = fmaf(x, 512.0f / 20.0f, 256.0f);
    tp = fminf(fmaxf(tp, 0.0f), 511.5f);
    const float2 c = tab[(int)tp];
    return fmaf(tp, c.y, c.x);
}

// =====================================================================
// Kernel A (persistent): [NNODE,64] @ BigW[64,576] -> UV | G1 | G2
// =====================================================================
__global__ __launch_bounds__(A_THR, 1)
void node_gemm_kernel(const float* __restrict__ z,
                      const float* __restrict__ Wffw,
                      const float* __restrict__ Wf,
                      const float* __restrict__ Ws)
{
    extern __shared__ char sm[];
    const uint32_t sb = smem_u32(sm);
    const int tid = threadIdx.x, wid = tid >> 5, lane = tid & 31;
    const int mi = wid >> 2, ni = wid & 3;

    for (int idx = tid; idx < 64 * 576; idx += A_THR) {
        const int k = idx / 576, j = idx - k * 576;
        float w;
        if (j < 160)      w = Wffw[k * 160 + j];
        else if (j < 320) w = Wffw[(64 + k) * 160 + (j - 160)];
        else if (j < 384) w = Wf[k * 64 + (j - 320)];
        else if (j < 448) w = Ws[k * 64 + (j - 384)];
        else if (j < 512) w = Wf[(64 + k) * 64 + (j - 448)];
        else              w = Ws[(64 + k) * 64 + (j - 512)];
        const __nv_bfloat16 h = __float2bfloat16(w);
        const __nv_bfloat16 l = __float2bfloat16(w - __bfloat162float(h));
        *reinterpret_cast<__nv_bfloat16*>(sm + A_WH + k * A_WSTR + j * 2) = h;
        *reinterpret_cast<__nv_bfloat16*>(sm + A_WL + k * A_WSTR + j * 2) = l;
    }

    const int r = tid >> 3, cq = (tid & 7) * 8;

    float4 va = make_float4(0.f, 0.f, 0.f, 0.f), vb = va;
    int t = blockIdx.x;
    if (t < A_NT) {
        const int grow = t * A_TILE + r;
        if (grow < NNODE) {
            const float4* zr = reinterpret_cast<const float4*>(z + (size_t)grow * 64 + cq);
            va = zr[0]; vb = zr[1];
        }
    }

    for (; t < A_NT; t += gridDim.x) {
        __syncthreads();

        {
            uint32_t* zh = reinterpret_cast<uint32_t*>(sm + A_ZH + r * A_ZSTR + cq * 2);
            uint32_t* zl = reinterpret_cast<uint32_t*>(sm + A_ZL + r * A_ZSTR + cq * 2);
            uint32_t h0, l0, h1, l1;
            split2(va.x, va.y, h0, l0); split2(va.z, va.w, h1, l1);
            zh[0] = h0; zh[1] = h1; zl[0] = l0; zl[1] = l1;
            split2(vb.x, vb.y, h0, l0); split2(vb.z, vb.w, h1, l1);
            zh[2] = h0; zh[3] = h1; zl[2] = l0; zl[3] = l1;
        }
        __syncthreads();

        const int tn = t + gridDim.x;
        va = make_float4(0.f, 0.f, 0.f, 0.f); vb = va;
        if (tn < A_NT) {
            const int grow = tn * A_TILE + r;
            if (grow < NNODE) {
                const float4* zr = reinterpret_cast<const float4*>(z + (size_t)grow * 64 + cq);
                va = zr[0]; vb = zr[1];
            }
        }

        float acc[18][4];
        #pragma unroll
        for (int n = 0; n < 18; n++)
            #pragma unroll
            for (int q = 0; q < 4; q++) acc[n][q] = 0.0f;

        #pragma unroll
        for (int k = 0; k < 4; k++) {
            uint32_t ah[4], al[4];
            const uint32_t arow = (uint32_t)(mi * 16 + (lane & 15)) * A_ZSTR
                                + (uint32_t)k * 32 + ((lane >> 4) << 4);
            ldm_x4(ah, sb + A_ZH + arow);
            ldm_x4(al, sb + A_ZL + arow);
            const uint32_t brow = (uint32_t)(k * 16 + (lane & 15)) * A_WSTR + (uint32_t)ni * 288;
            #pragma unroll
            for (int n = 0; n < 18; n++) {
                uint32_t bh[2], bl[2];
                ldm_x2t(bh, sb + A_WH + brow + n * 16);
                ldm_x2t(bl, sb + A_WL + brow + n * 16);
                mma_bf16(acc[n], ah, bh);
                mma_bf16(acc[n], al, bh);
                mma_bf16(acc[n], ah, bl);
            }
        }

        const int r0 = t * A_TILE + mi * 16 + (lane >> 2);
        const int r1 = r0 + 8;
        #pragma unroll
        for (int n = 0; n < 18; n++) {
            const int j = ni * 144 + n * 8 + 2 * (lane & 3);
            if (r0 < NNODE) {
                float2 o; o.x = acc[n][0]; o.y = acc[n][1];
                *reinterpret_cast<float2*>(scratch_ptr(r0, j)) = o;
            }
            if (r1 < NNODE) {
                float2 o; o.x = acc[n][2]; o.y = acc[n][3];
                *reinterpret_cast<float2*>(scratch_ptr(r1, j)) = o;
            }
        }
    }
}

// =====================================================================
// Kernel F (fused): per 64-edge tile
//   z_edge[e] = relu(U[src] + V[dst] + ea[e]@W3 + b)
//   z_node[dst] += sigmoid(P[dst]+Q[src]+bf) * softplus(R[dst]+S[src]+bs)
// =====================================================================
__global__ __launch_bounds__(F_THR, 3)
void edge_gate_kernel(const float* __restrict__ ea,
                      const int*   __restrict__ srcp,
                      const int*   __restrict__ dstp,
                      const float* __restrict__ Wffw,
                      const float* __restrict__ bias,
                      const float* __restrict__ bf,
                      const float* __restrict__ bs,
                      float* __restrict__ z_edge,
                      float* __restrict__ z_node)
{
    extern __shared__ char sm[];
    const uint32_t sb = smem_u32(sm);
    const int tid = threadIdx.x, wid = tid >> 5, lane = tid & 31;
    const int mi = wid >> 2, ni = wid & 3;

    // ---- one-time init: W3 hi/lo, bias, LUTs, gate biases ----
    for (int idx = tid; idx < 32 * 160; idx += F_THR) {
        const int k = idx / 160, n = idx - k * 160;
        const float w = Wffw[(128 + k) * 160 + n];
        const __nv_bfloat16 h = __float2bfloat16(w);
        const __nv_bfloat16 l = __float2bfloat16(w - __bfloat162float(h));
        *reinterpret_cast<__nv_bfloat16*>(sm + F_WH + k * F_WSTR + n * 2) = h;
        *reinterpret_cast<__nv_bfloat16*>(sm + F_WL + k * F_WSTR + n * 2) = l;
    }
    if (tid < 160) reinterpret_cast<float*>(sm + F_BIAS)[tid] = bias[tid];
    for (int i = tid; i < 512; i += F_THR) {
        const float x0 = -10.0f + (float)i * (20.0f / 512.0f);
        const float x1 = x0 + (20.0f / 512.0f);
        const float s0 = 1.0f / (1.0f + expf(-x0));
        const float s1 = 1.0f / (1.0f + expf(-x1));
        const float ds = s1 - s0;
        reinterpret_cast<float2*>(sm + F_LSIG)[i] = make_float2(s0 - (float)i * ds, ds);
        const float p0 = fmaxf(x0, 0.0f) + log1pf(expf(-fabsf(x0)));
        const float p1 = fmaxf(x1, 0.0f) + log1pf(expf(-fabsf(x1)));
        const float dp = p1 - p0;
        reinterpret_cast<float2*>(sm + F_LSP)[i] = make_float2(p0 - (float)i * dp, dp);
    }
    if (tid < 64) {
        reinterpret_cast<float*>(sm + F_BF)[tid] = bf[tid];
        reinterpret_cast<float*>(sm + F_BS)[tid] = bs[tid];
    }

    const float*  s_bias = reinterpret_cast<const float*>(sm + F_BIAS);
    const float2* t_sig  = reinterpret_cast<const float2*>(sm + F_LSIG);
    const float2* t_sp   = reinterpret_cast<const float2*>(sm + F_LSP);
    const float*  s_bf   = reinterpret_cast<const float*>(sm + F_BF);
    const float*  s_bs   = reinterpret_cast<const float*>(sm + F_BS);
    const int e_loc = tid >> 2, q = tid & 3;

    for (int t = blockIdx.x; t < F_NT; t += gridDim.x) {
        __syncthreads();

        // ---- phase 1: ea tile -> smem (bf16 hi/lo) ----
        {
            const int ge = t * F_TILE + e_loc;
            const float4* ep = reinterpret_cast<const float4*>(ea + (size_t)ge * 32) + q * 2;
            const float4 a = ep[0], b = ep[1];
            uint32_t* xh = reinterpret_cast<uint32_t*>(sm + F_EH + e_loc * F_ESTR + q * 16);
            uint32_t* xl = reinterpret_cast<uint32_t*>(sm + F_EL + e_loc * F_ESTR + q * 16);
            uint32_t h0, l0, h1, l1;
            split2(a.x, a.y, h0, l0); split2(a.z, a.w, h1, l1);
            xh[0] = h0; xh[1] = h1; xl[0] = l0; xl[1] = l1;
            split2(b.x, b.y, h0, l0); split2(b.z, b.w, h1, l1);
            xh[2] = h0; xh[3] = h1; xl[2] = l0; xl[3] = l1;
        }
        __syncthreads();

        // ---- phase 2: GEMM ea@W3 (K=32) ----
        float acc[2][5][4];
        #pragma unroll
        for (int m = 0; m < 2; m++)
            #pragma unroll
            for (int n = 0; n < 5; n++)
                #pragma unroll
                for (int r = 0; r < 4; r++) acc[m][n][r] = 0.0f;

        #pragma unroll
        for (int k = 0; k < 2; k++) {
            uint32_t ah[2][4], al[2][4];
            const uint32_t arow = (uint32_t)(mi * 32 + (lane & 15)) * F_ESTR
                                + (uint32_t)k * 32 + ((lane >> 4) << 4);
            #pragma unroll
            for (int m = 0; m < 2; m++) {
                ldm_x4(ah[m], sb + F_EH + arow + m * 16 * F_ESTR);
                ldm_x4(al[m], sb + F_EL + arow + m * 16 * F_ESTR);
            }
            const uint32_t brow = (uint32_t)(k * 16 + (lane & 15)) * F_WSTR + (uint32_t)ni * 80;
            #pragma unroll
            for (int n = 0; n < 5; n++) {
                uint32_t bh[2], bl[2];
                ldm_x2t(bh, sb + F_WH + brow + n * 16);
                ldm_x2t(bl, sb + F_WL + brow + n * 16);
                #pragma unroll
                for (int m = 0; m < 2; m++) {
                    mma_bf16(acc[m][n], ah[m], bh);
                    mma_bf16(acc[m][n], al[m], bh);
                    mma_bf16(acc[m][n], ah[m], bl);
                }
            }
        }

        // ---- phase 3: z_edge epilogue (front-batched U/V gather) ----
        #pragma unroll
        for (int m = 0; m < 2; m++) {
            const int r0 = t * F_TILE + mi * 32 + m * 16 + (lane >> 2);
            const int r1 = r0 + 8;
            const int s0 = srcp[r0], d0 = dstp[r0];
            const int s1 = srcp[r1], d1 = dstp[r1];
            const float* U0 = g_UV + (size_t)s0 * 320;
            const float* V0 = g_UV + (size_t)d0 * 320 + 160;
            const float* U1 = g_UV + (size_t)s1 * 320;
            const float* V1 = g_UV + (size_t)d1 * 320 + 160;
            const int jb = ni * 40 + 2 * (lane & 3);

            float2 t0[5], t1[5];
            #pragma unroll
            for (int n = 0; n < 5; n++) {
                const int j = jb + n * 8;
                const float2 u0 = *reinterpret_cast<const float2*>(U0 + j);
                const float2 v0 = *reinterpret_cast<const float2*>(V0 + j);
                const float2 u1 = *reinterpret_cast<const float2*>(U1 + j);
                const float2 v1 = *reinterpret_cast<const float2*>(V1 + j);
                t0[n].x = u0.x + v0.x; t0[n].y = u0.y + v0.y;
                t1[n].x = u1.x + v1.x; t1[n].y = u1.y + v1.y;
            }
            #pragma unroll
            for (int n = 0; n < 5; n++) {
                const int j = jb + n * 8;
                const float b0 = s_bias[j], b1 = s_bias[j + 1];
                float2 o0, o1;
                o0.x = fmaxf(acc[m][n][0] + t0[n].x + b0, 0.0f);
                o0.y = fmaxf(acc[m][n][1] + t0[n].y + b1, 0.0f);
                o1.x = fmaxf(acc[m][n][2] + t1[n].x + b0, 0.0f);
                o1.y = fmaxf(acc[m][n][3] + t1[n].y + b1, 0.0f);
                *reinterpret_cast<float2*>(z_edge + (size_t)r0 * 160 + j) = o0;
                *reinterpret_cast<float2*>(z_edge + (size_t)r1 * 160 + j) = o1;
            }
        }

        // ---- phase 4: gate + scatter (4 threads/edge, 16 cols each) ----
        {
            const int e = t * F_TILE + e_loc;
            const int c0 = q * 16;
            const int d = dstp[e], s = srcp[e];
            const float4* Pf = reinterpret_cast<const float4*>(g_G1 + (size_t)d * 128 + c0);
            const float4* Qf = reinterpret_cast<const float4*>(g_G2 + (size_t)s * 128 + c0);
            const float4* Ps = reinterpret_cast<const float4*>(g_G1 + (size_t)d * 128 + 64 + c0);
            const float4* Qs = reinterpret_cast<const float4*>(g_G2 + (size_t)s * 128 + 64 + c0);
            float* out = z_node + (size_t)d * 64 + c0;

            #pragma unroll
            for (int half = 0; half < 2; half++) {
                float4 pf[2], qf[2], ps[2], qs[2];
                #pragma unroll
                for (int j = 0; j < 2; j++) {
                    const int jj = half * 2 + j;
                    pf[j] = Pf[jj]; qf[j] = Qf[jj]; ps[j] = Ps[jj]; qs[j] = Qs[jj];
                }
                #pragma unroll
                for (int j = 0; j < 2; j++) {
                    const int jj = half * 2 + j;
                    const int c = c0 + 4 * jj;
                    float4 msg;
                    {
                        const float f = pf[j].x + qf[j].x + s_bf[c + 0];
                        const float v = ps[j].x + qs[j].x + s_bs[c + 0];
                        msg.x = lut_eval(t_sig, f) * fmaxf(lut_eval(t_sp, v), v);
                    }
                    {
                        const float f = pf[j].y + qf[j].y + s_bf[c + 1];
                        const float v = ps[j].y + qs[j].y + s_bs[c + 1];
                        msg.y = lut_eval(t_sig, f) * fmaxf(lut_eval(t_sp, v), v);
                    }
                    {
                        const float f = pf[j].z + qf[j].z + s_bf[c + 2];
                        const float v = ps[j].z + qs[j].z + s_bs[c + 2];
                        msg.z = lut_eval(t_sig, f) * fmaxf(lut_eval(t_sp, v), v);
                    }
                    {
                        const float f = pf[j].w + qf[j].w + s_bf[c + 3];
                        const float v = ps[j].w + qs[j].w + s_bs[c + 3];
                        msg.w = lut_eval(t_sig, f) * fmaxf(lut_eval(t_sp, v), v);
                    }
                    atomicAdd(reinterpret_cast<float4*>(out + 4 * jj), msg);
                }
            }
        }
    }
}

extern "C" void kernel_launch(void* const* d_in, const int* in_sizes, int n_in,
                              void* d_out, int out_size)
{
    const float* z    = (const float*)d_in[0];
    const float* ea   = (const float*)d_in[1];
    const int*   eidx = (const int*)  d_in[2];
    const float* Wffw = (const float*)d_in[3];
    const float* bffw = (const float*)d_in[4];
    const float* Wf   = (const float*)d_in[5];
    const float* bf   = (const float*)d_in[6];
    const float* Ws   = (const float*)d_in[7];
    const float* bs   = (const float*)d_in[8];

    float* z_node = (float*)d_out;
    float* z_edge = (float*)d_out + (size_t)NNODE * 64;
    const int* srcp = eidx;
    const int* dstp = eidx + NE;

    static bool init = false;
    if (!init) {
        init = true;
        cudaFuncSetAttribute(node_gemm_kernel, cudaFuncAttributeMaxDynamicSharedMemorySize, A_SMEM);
        cudaFuncSetAttribute(edge_gate_kernel, cudaFuncAttributeMaxDynamicSharedMemorySize, F_SMEM);
    }

    // residual base for scatter-add
    cudaMemcpyAsync(z_node, z, (size_t)NNODE * 64 * sizeof(float),
                    cudaMemcpyDeviceToDevice, 0);
    node_gemm_kernel<<<148, A_THR, A_SMEM, 0>>>(z, Wffw, Wf, Ws);
    edge_gate_kernel<<<444, F_THR, F_SMEM, 0>>>(ea, srcp, dstp, Wffw, bffw,
                                                bf, bs, z_edge, z_node);
}

// round 12
// speedup vs baseline: 1.5823x; 1.0058x over previous
#include <cuda_runtime.h>
#include <cuda_bf16.h>
#include <cstdint>
#include <math.h>

#define NE      800000
#define NNODE   50000

// ---------------- scratch (static device arrays; no allocation) ----------------
__device__ float g_UV[(size_t)NNODE * 320];   // [n][0:160]=U=z@W1, [160:320]=V=z@W2
__device__ float g_G1[(size_t)NNODE * 128];   // [n][0:64]=P, [64:128]=R
__device__ float g_G2[(size_t)NNODE * 128];   // [n][0:64]=Q, [64:128]=S

// ---------------- kernel A (node GEMM, persistent) ----------------
#define A_THR  512
#define A_TILE 64
#define A_NT   ((NNODE + A_TILE - 1) / A_TILE)
#define A_ZSTR 144
#define A_WSTR 1168
#define A_ZH   0
#define A_ZL   (A_ZH + 64 * A_ZSTR)
#define A_WH   (A_ZL + 64 * A_ZSTR)
#define A_WL   (A_WH + 64 * A_WSTR)
#define A_SMEM (A_WL + 64 * A_WSTR)              // 167936

// ---------------- kernel F (fused, transposed epilogue) ----------------
#define F_THR   256
#define F_TILE  64
#define F_NT    (NE / F_TILE)                    // 12500
#define F_ESTR  80                               // ea tile row stride (bytes)
#define F_WSTR  336
#define F_DSTR  168                              // D tile row stride (floats)
#define F_WH    0
#define F_WL    (F_WH + 32 * F_WSTR)             // 10752
#define F_BIAS  (F_WL + 32 * F_WSTR)             // 21504
#define F_LSIG  (F_BIAS + 640)                   // 22144
#define F_LSP   (F_LSIG + 4096)                  // 26240
#define F_BF    (F_LSP + 4096)                   // 30336
#define F_BS    (F_BF + 256)                     // 30592
#define F_UNI   (F_BS + 256)                     // 30848: E-tile (10240 B) / D-tile (43008 B)
#define F_EH    (F_UNI)
#define F_EL    (F_UNI + 64 * F_ESTR)
#define F_SMEM  (F_UNI + 64 * F_DSTR * 4)        // 73856 -> 3 CTAs/SM

static __device__ __forceinline__ uint32_t smem_u32(const void* p) {
    uint32_t a;
    asm("{ .reg .u64 t; cvta.to.shared.u64 t, %1; cvt.u32.u64 %0, t; }" : "=r"(a) : "l"(p));
    return a;
}
static __device__ __forceinline__ void ldm_x4(uint32_t* r, uint32_t addr) {
    asm volatile("ldmatrix.sync.aligned.m8n8.x4.shared.b16 {%0,%1,%2,%3}, [%4];"
                 : "=r"(r[0]), "=r"(r[1]), "=r"(r[2]), "=r"(r[3]) : "r"(addr));
}
static __device__ __forceinline__ void ldm_x2t(uint32_t* r, uint32_t addr) {
    asm volatile("ldmatrix.sync.aligned.m8n8.x2.trans.shared.b16 {%0,%1}, [%2];"
                 : "=r"(r[0]), "=r"(r[1]) : "r"(addr));
}
static __device__ __forceinline__ void mma_bf16(float* c, const uint32_t* a, const uint32_t* b) {
    asm volatile("mma.sync.aligned.m16n8k16.row.col.f32.bf16.bf16.f32 "
                 "{%0,%1,%2,%3}, {%4,%5,%6,%7}, {%8,%9}, {%0,%1,%2,%3};"
                 : "+f"(c[0]), "+f"(c[1]), "+f"(c[2]), "+f"(c[3])
                 : "r"(a[0]), "r"(a[1]), "r"(a[2]), "r"(a[3]), "r"(b[0]), "r"(b[1]));
}
static __device__ __forceinline__ void split2(float x0, float x1, uint32_t& hi, uint32_t& lo) {
    uint32_t h;
    asm("cvt.rn.bf16x2.f32 %0, %1, %2;" : "=r"(h) : "f"(x1), "f"(x0));
    float h0 = __uint_as_float(h << 16);
    float h1 = __uint_as_float(h & 0xFFFF0000u);
    uint32_t l;
    asm("cvt.rn.bf16x2.f32 %0, %1, %2;" : "=r"(l) : "f"(x1 - h1), "f"(x0 - h0));
    hi = h; lo = l;
}
static __device__ __forceinline__ float* scratch_ptr(int row, int j) {
    if (j < 320) return g_UV + (size_t)row * 320 + j;
    if (j < 448) return g_G1 + (size_t)row * 128 + (j - 320);
    return g_G2 + (size_t)row * 128 + (j - 448);
}
static __device__ __forceinline__ float lut_eval(const float2* tab, float x) {
    float tp = fmaf(x, 512.0f / 20.0f, 256.0f);
    tp = fminf(fmaxf(tp, 0.0f), 511.5f);
    const float2 c = tab[(int)tp];
    return fmaf(tp, c.y, c.x);
}

// =====================================================================
// Kernel A (persistent): [NNODE,64] @ BigW[64,576] -> UV | G1 | G2
// =====================================================================
__global__ __launch_bounds__(A_THR, 1)
void node_gemm_kernel(const float* __restrict__ z,
                      const float* __restrict__ Wffw,
                      const float* __restrict__ Wf,
                      const float* __restrict__ Ws)
{
    extern __shared__ char sm[];
    const uint32_t sb = smem_u32(sm);
    const int tid = threadIdx.x, wid = tid >> 5, lane = tid & 31;
    const int mi = wid >> 2, ni = wid & 3;

    for (int idx = tid; idx < 64 * 576; idx += A_THR) {
        const int k = idx / 576, j = idx - k * 576;
        float w;
        if (j < 160)      w = Wffw[k * 160 + j];
        else if (j < 320) w = Wffw[(64 + k) * 160 + (j - 160)];
        else if (j < 384) w = Wf[k * 64 + (j - 320)];
        else if (j < 448) w = Ws[k * 64 + (j - 384)];
        else if (j < 512) w = Wf[(64 + k) * 64 + (j - 448)];
        else              w = Ws[(64 + k) * 64 + (j - 512)];
        const __nv_bfloat16 h = __float2bfloat16(w);
        const __nv_bfloat16 l = __float2bfloat16(w - __bfloat162float(h));
        *reinterpret_cast<__nv_bfloat16*>(sm + A_WH + k * A_WSTR + j * 2) = h;
        *reinterpret_cast<__nv_bfloat16*>(sm + A_WL + k * A_WSTR + j * 2) = l;
    }

    const int r = tid >> 3, cq = (tid & 7) * 8;

    float4 va = make_float4(0.f, 0.f, 0.f, 0.f), vb = va;
    int t = blockIdx.x;
    if (t < A_NT) {
        const int grow = t * A_TILE + r;
        if (grow < NNODE) {
            const float4* zr = reinterpret_cast<const float4*>(z + (size_t)grow * 64 + cq);
            va = zr[0]; vb = zr[1];
        }
    }

    for (; t < A_NT; t += gridDim.x) {
        __syncthreads();

        {
            uint32_t* zh = reinterpret_cast<uint32_t*>(sm + A_ZH + r * A_ZSTR + cq * 2);
            uint32_t* zl = reinterpret_cast<uint32_t*>(sm + A_ZL + r * A_ZSTR + cq * 2);
            uint32_t h0, l0, h1, l1;
            split2(va.x, va.y, h0, l0); split2(va.z, va.w, h1, l1);
            zh[0] = h0; zh[1] = h1; zl[0] = l0; zl[1] = l1;
            split2(vb.x, vb.y, h0, l0); split2(vb.z, vb.w, h1, l1);
            zh[2] = h0; zh[3] = h1; zl[2] = l0; zl[3] = l1;
        }
        __syncthreads();

        const int tn = t + gridDim.x;
        va = make_float4(0.f, 0.f, 0.f, 0.f); vb = va;
        if (tn < A_NT) {
            const int grow = tn * A_TILE + r;
            if (grow < NNODE) {
                const float4* zr = reinterpret_cast<const float4*>(z + (size_t)grow * 64 + cq);
                va = zr[0]; vb = zr[1];
            }
        }

        float acc[18][4];
        #pragma unroll
        for (int n = 0; n < 18; n++)
            #pragma unroll
            for (int q = 0; q < 4; q++) acc[n][q] = 0.0f;

        #pragma unroll
        for (int k = 0; k < 4; k++) {
            uint32_t ah[4], al[4];
            const uint32_t arow = (uint32_t)(mi * 16 + (lane & 15)) * A_ZSTR
                                + (uint32_t)k * 32 + ((lane >> 4) << 4);
            ldm_x4(ah, sb + A_ZH + arow);
            ldm_x4(al, sb + A_ZL + arow);
            const uint32_t brow = (uint32_t)(k * 16 + (lane & 15)) * A_WSTR + (uint32_t)ni * 288;
            #pragma unroll
            for (int n = 0; n < 18; n++) {
                uint32_t bh[2], bl[2];
                ldm_x2t(bh, sb + A_WH + brow + n * 16);
                ldm_x2t(bl, sb + A_WL + brow + n * 16);
                mma_bf16(acc[n], ah, bh);
                mma_bf16(acc[n], al, bh);
                mma_bf16(acc[n], ah, bl);
            }
        }

        const int r0 = t * A_TILE + mi * 16 + (lane >> 2);
        const int r1 = r0 + 8;
        #pragma unroll
        for (int n = 0; n < 18; n++) {
            const int j = ni * 144 + n * 8 + 2 * (lane & 3);
            if (r0 < NNODE) {
                float2 o; o.x = acc[n][0]; o.y = acc[n][1];
                *reinterpret_cast<float2*>(scratch_ptr(r0, j)) = o;
            }
            if (r1 < NNODE) {
                float2 o; o.x = acc[n][2]; o.y = acc[n][3];
                *reinterpret_cast<float2*>(scratch_ptr(r1, j)) = o;
            }
        }
    }
}

// =====================================================================
// Kernel F (fused, line-coalesced epilogues):
//   z_edge[e] = relu(U[src] + V[dst] + ea[e]@W3 + b)
//   z_node[dst] += sigmoid(P[dst]+Q[src]+bf) * softplus(R[dst]+S[src]+bs)
// =====================================================================
__global__ __launch_bounds__(F_THR, 3)
void edge_gate_kernel(const float* __restrict__ ea,
                      const int*   __restrict__ srcp,
                      const int*   __restrict__ dstp,
                      const float* __restrict__ Wffw,
                      const float* __restrict__ bias,
                      const float* __restrict__ bf,
                      const float* __restrict__ bs,
                      float* __restrict__ z_edge,
                      float* __restrict__ z_node)
{
    extern __shared__ char sm[];
    const uint32_t sb = smem_u32(sm);
    const int tid = threadIdx.x, wid = tid >> 5, lane = tid & 31;
    const int mi = wid >> 2, ni = wid & 3;

    // ---- one-time init ----
    for (int idx = tid; idx < 32 * 160; idx += F_THR) {
        const int k = idx / 160, n = idx - k * 160;
        const float w = Wffw[(128 + k) * 160 + n];
        const __nv_bfloat16 h = __float2bfloat16(w);
        const __nv_bfloat16 l = __float2bfloat16(w - __bfloat162float(h));
        *reinterpret_cast<__nv_bfloat16*>(sm + F_WH + k * F_WSTR + n * 2) = h;
        *reinterpret_cast<__nv_bfloat16*>(sm + F_WL + k * F_WSTR + n * 2) = l;
    }
    if (tid < 160) reinterpret_cast<float*>(sm + F_BIAS)[tid] = bias[tid];
    for (int i = tid; i < 512; i += F_THR) {
        const float x0 = -10.0f + (float)i * (20.0f / 512.0f);
        const float x1 = x0 + (20.0f / 512.0f);
        const float s0 = 1.0f / (1.0f + expf(-x0));
        const float s1 = 1.0f / (1.0f + expf(-x1));
        const float ds = s1 - s0;
        reinterpret_cast<float2*>(sm + F_LSIG)[i] = make_float2(s0 - (float)i * ds, ds);
        const float p0 = fmaxf(x0, 0.0f) + log1pf(expf(-fabsf(x0)));
        const float p1 = fmaxf(x1, 0.0f) + log1pf(expf(-fabsf(x1)));
        const float dp = p1 - p0;
        reinterpret_cast<float2*>(sm + F_LSP)[i] = make_float2(p0 - (float)i * dp, dp);
    }
    if (tid < 64) {
        reinterpret_cast<float*>(sm + F_BF)[tid] = bf[tid];
        reinterpret_cast<float*>(sm + F_BS)[tid] = bs[tid];
    }

    const float*  s_bias = reinterpret_cast<const float*>(sm + F_BIAS);
    const float2* t_sig  = reinterpret_cast<const float2*>(sm + F_LSIG);
    const float2* t_sp   = reinterpret_cast<const float2*>(sm + F_LSP);
    const float*  s_bf   = reinterpret_cast<const float*>(sm + F_BF);
    const float*  s_bs   = reinterpret_cast<const float*>(sm + F_BS);

    const int e_q  = tid >> 2, q   = tid & 3;    // phase-1 mapping (4 thr/edge)
    const int e_o  = tid >> 3, oct = tid & 7;    // phase-3b/4 mapping (8 thr/edge)

    for (int t = blockIdx.x; t < F_NT; t += gridDim.x) {
        __syncthreads();   // prev tile's D reads done; E region reusable

        // ---- phase 1: ea tile -> smem (bf16 hi/lo) ----
        {
            const int ge = t * F_TILE + e_q;
            const float4* ep = reinterpret_cast<const float4*>(ea + (size_t)ge * 32) + q * 2;
            const float4 a = ep[0], b = ep[1];
            uint32_t* xh = reinterpret_cast<uint32_t*>(sm + F_EH + e_q * F_ESTR + q * 16);
            uint32_t* xl = reinterpret_cast<uint32_t*>(sm + F_EL + e_q * F_ESTR + q * 16);
            uint32_t h0, l0, h1, l1;
            split2(a.x, a.y, h0, l0); split2(a.z, a.w, h1, l1);
            xh[0] = h0; xh[1] = h1; xl[0] = l0; xl[1] = l1;
            split2(b.x, b.y, h0, l0); split2(b.z, b.w, h1, l1);
            xh[2] = h0; xh[3] = h1; xl[2] = l0; xl[3] = l1;
        }
        __syncthreads();

        // ---- phase 2: GEMM ea@W3 (K=32) ----
        float acc[2][5][4];
        #pragma unroll
        for (int m = 0; m < 2; m++)
            #pragma unroll
            for (int n = 0; n < 5; n++)
                #pragma unroll
                for (int r = 0; r < 4; r++) acc[m][n][r] = 0.0f;

        #pragma unroll
        for (int k = 0; k < 2; k++) {
            uint32_t ah[2][4], al[2][4];
            const uint32_t arow = (uint32_t)(mi * 32 + (lane & 15)) * F_ESTR
                                + (uint32_t)k * 32 + ((lane >> 4) << 4);
            #pragma unroll
            for (int m = 0; m < 2; m++) {
                ldm_x4(ah[m], sb + F_EH + arow + m * 16 * F_ESTR);
                ldm_x4(al[m], sb + F_EL + arow + m * 16 * F_ESTR);
            }
            const uint32_t brow = (uint32_t)(k * 16 + (lane & 15)) * F_WSTR + (uint32_t)ni * 80;
            #pragma unroll
            for (int n = 0; n < 5; n++) {
                uint32_t bh[2], bl[2];
                ldm_x2t(bh, sb + F_WH + brow + n * 16);
                ldm_x2t(bl, sb + F_WL + brow + n * 16);
                #pragma unroll
                for (int m = 0; m < 2; m++) {
                    mma_bf16(acc[m][n], ah[m], bh);
                    mma_bf16(acc[m][n], al[m], bh);
                    mma_bf16(acc[m][n], ah[m], bl);
                }
            }
        }
        __syncthreads();   // all warps done reading E before D overwrites it

        // ---- phase 3a: stage acc -> D tile (smem) ----
        {
            float* D = reinterpret_cast<float*>(sm + F_UNI);
            #pragma unroll
            for (int m = 0; m < 2; m++) {
                const int row = mi * 32 + m * 16 + (lane >> 2);
                #pragma unroll
                for (int n = 0; n < 5; n++) {
                    const int j = ni * 40 + n * 8 + 2 * (lane & 3);
                    float2 o0, o1;
                    o0.x = acc[m][n][0]; o0.y = acc[m][n][1];
                    o1.x = acc[m][n][2]; o1.y = acc[m][n][3];
                    *reinterpret_cast<float2*>(D + row * F_DSTR + j) = o0;
                    *reinterpret_cast<float2*>(D + (row + 8) * F_DSTR + j) = o1;
                }
            }
        }
        __syncthreads();

        // ---- phase 3b: coalesced epilogue (8 thr/edge, float4 lanes) ----
        #pragma unroll
        for (int eh = 0; eh < 2; eh++) {
            const int le = e_o + 32 * eh;
            const int ge = t * F_TILE + le;
            const int s = srcp[ge], d = dstp[ge];
            const float4* U = reinterpret_cast<const float4*>(g_UV + (size_t)s * 320);
            const float4* V = reinterpret_cast<const float4*>(g_UV + (size_t)d * 320 + 160);
            const float4* D = reinterpret_cast<const float4*>(sm + F_UNI) + le * (F_DSTR / 4);
            const float4* B = reinterpret_cast<const float4*>(s_bias);
            float4* O = reinterpret_cast<float4*>(z_edge + (size_t)ge * 160);

            float4 u[5], v[5];
            #pragma unroll
            for (int i = 0; i < 5; i++) u[i] = U[oct + 8 * i];
            #pragma unroll
            for (int i = 0; i < 5; i++) v[i] = V[oct + 8 * i];
            #pragma unroll
            for (int i = 0; i < 5; i++) {
                const int c4 = oct + 8 * i;
                const float4 dd = D[c4], bb = B[c4];
                float4 o;
                o.x = fmaxf(dd.x + u[i].x + v[i].x + bb.x, 0.0f);
                o.y = fmaxf(dd.y + u[i].y + v[i].y + bb.y, 0.0f);
                o.z = fmaxf(dd.z + u[i].z + v[i].z + bb.z, 0.0f);
                o.w = fmaxf(dd.w + u[i].w + v[i].w + bb.w, 0.0f);
                O[c4] = o;
            }

            // ---- phase 4: gate + scatter for the same edge ----
            const float4* Pf = reinterpret_cast<const float4*>(g_G1 + (size_t)d * 128);
            const float4* Qf = reinterpret_cast<const float4*>(g_G2 + (size_t)s * 128);
            const float4* Ps = Pf + 16;
            const float4* Qs = Qf + 16;
            const float4* Bf = reinterpret_cast<const float4*>(s_bf);
            const float4* Bs = reinterpret_cast<const float4*>(s_bs);
            float4* out = reinterpret_cast<float4*>(z_node + (size_t)d * 64);

            float4 pf[2], qf[2], ps[2], qs[2];
            #pragma unroll
            for (int i = 0; i < 2; i++) pf[i] = Pf[oct + 8 * i];
            #pragma unroll
            for (int i = 0; i < 2; i++) qf[i] = Qf[oct + 8 * i];
            #pragma unroll
            for (int i = 0; i < 2; i++) ps[i] = Ps[oct + 8 * i];
            #pragma unroll
            for (int i = 0; i < 2; i++) qs[i] = Qs[oct + 8 * i];

            #pragma unroll
            for (int i = 0; i < 2; i++) {
                const int c4 = oct + 8 * i;
                const float4 bfv = Bf[c4], bsv = Bs[c4];
                float4 msg;
                {
                    const float f = pf[i].x + qf[i].x + bfv.x;
                    const float vv = ps[i].x + qs[i].x + bsv.x;
                    msg.x = lut_eval(t_sig, f) * fmaxf(lut_eval(t_sp, vv), vv);
                }
                {
                    const float f = pf[i].y + qf[i].y + bfv.y;
                    const float vv = ps[i].y + qs[i].y + bsv.y;
                    msg.y = lut_eval(t_sig, f) * fmaxf(lut_eval(t_sp, vv), vv);
                }
                {
                    const float f = pf[i].z + qf[i].z + bfv.z;
                    const float vv = ps[i].z + qs[i].z + bsv.z;
                    msg.z = lut_eval(t_sig, f) * fmaxf(lut_eval(t_sp, vv), vv);
                }
                {
                    const float f = pf[i].w + qf[i].w + bfv.w;
                    const float vv = ps[i].w + qs[i].w + bsv.w;
                    msg.w = lut_eval(t_sig, f) * fmaxf(lut_eval(t_sp, vv), vv);
                }
                atomicAdd(&out[c4], msg);
            }
        }
    }
}

extern "C" void kernel_launch(void* const* d_in, const int* in_sizes, int n_in,
                              void* d_out, int out_size)
{
    const float* z    = (const float*)d_in[0];
    const float* ea   = (const float*)d_in[1];
    const int*   eidx = (const int*)  d_in[2];
    const float* Wffw = (const float*)d_in[3];
    const float* bffw = (const float*)d_in[4];
    const float* Wf   = (const float*)d_in[5];
    const float* bf   = (const float*)d_in[6];
    const float* Ws   = (const float*)d_in[7];
    const float* bs   = (const float*)d_in[8];

    float* z_node = (float*)d_out;
    float* z_edge = (float*)d_out + (size_t)NNODE * 64;
    const int* srcp = eidx;
    const int* dstp = eidx + NE;

    static bool init = false;
    if (!init) {
        init = true;
        cudaFuncSetAttribute(node_gemm_kernel, cudaFuncAttributeMaxDynamicSharedMemorySize, A_SMEM);
        cudaFuncSetAttribute(edge_gate_kernel, cudaFuncAttributeMaxDynamicSharedMemorySize, F_SMEM);
    }

    // residual base for scatter-add
    cudaMemcpyAsync(z_node, z, (size_t)NNODE * 64 * sizeof(float),
                    cudaMemcpyDeviceToDevice, 0);
    node_gemm_kernel<<<148, A_THR, A_SMEM, 0>>>(z, Wffw, Wf, Ws);
    edge_gate_kernel<<<444, F_THR, F_SMEM, 0>>>(ea, srcp, dstp, Wffw, bffw,
                                                bf, bs, z_edge, z_node);
}

// round 13
// speedup vs baseline: 1.6148x; 1.0206x over previous
#include <cuda_runtime.h>
#include <cuda_bf16.h>
#include <cstdint>
#include <math.h>

#define NE      800000
#define NNODE   50000

// ---------------- scratch (static device arrays; no allocation) ----------------
__device__ float g_UV[(size_t)NNODE * 320];   // [n][0:160]=U=z@W1, [160:320]=V=z@W2
__device__ float g_G1[(size_t)NNODE * 128];   // [n][0:64]=P, [64:128]=R
__device__ float g_G2[(size_t)NNODE * 128];   // [n][0:64]=Q, [64:128]=S

// ---------------- kernel A (node GEMM, persistent) ----------------
#define A_THR  512
#define A_TILE 64
#define A_NT   ((NNODE + A_TILE - 1) / A_TILE)
#define A_ZSTR 144
#define A_WSTR 1168
#define A_ZH   0
#define A_ZL   (A_ZH + 64 * A_ZSTR)
#define A_WH   (A_ZL + 64 * A_ZSTR)
#define A_WL   (A_WH + 64 * A_WSTR)
#define A_SMEM (A_WL + 64 * A_WSTR)              // 167936

// ---------------- kernel F (fused, line-coalesced + cache-policied) ----------------
#define F_THR   256
#define F_TILE  64
#define F_NT    (NE / F_TILE)                    // 12500
#define F_ESTR  80
#define F_WSTR  336
#define F_DSTR  168
#define F_WH    0
#define F_WL    (F_WH + 32 * F_WSTR)
#define F_BIAS  (F_WL + 32 * F_WSTR)
#define F_LSIG  (F_BIAS + 640)
#define F_LSP   (F_LSIG + 4096)
#define F_BF    (F_LSP + 4096)
#define F_BS    (F_BF + 256)
#define F_UNI   (F_BS + 256)
#define F_EH    (F_UNI)
#define F_EL    (F_UNI + 64 * F_ESTR)
#define F_SMEM  (F_UNI + 64 * F_DSTR * 4)        // 73856 -> 3 CTAs/SM

static __device__ __forceinline__ uint32_t smem_u32(const void* p) {
    uint32_t a;
    asm("{ .reg .u64 t; cvta.to.shared.u64 t, %1; cvt.u32.u64 %0, t; }" : "=r"(a) : "l"(p));
    return a;
}
static __device__ __forceinline__ void ldm_x4(uint32_t* r, uint32_t addr) {
    asm volatile("ldmatrix.sync.aligned.m8n8.x4.shared.b16 {%0,%1,%2,%3}, [%4];"
                 : "=r"(r[0]), "=r"(r[1]), "=r"(r[2]), "=r"(r[3]) : "r"(addr));
}
static __device__ __forceinline__ void ldm_x2t(uint32_t* r, uint32_t addr) {
    asm volatile("ldmatrix.sync.aligned.m8n8.x2.trans.shared.b16 {%0,%1}, [%2];"
                 : "=r"(r[0]), "=r"(r[1]) : "r"(addr));
}
static __device__ __forceinline__ void mma_bf16(float* c, const uint32_t* a, const uint32_t* b) {
    asm volatile("mma.sync.aligned.m16n8k16.row.col.f32.bf16.bf16.f32 "
                 "{%0,%1,%2,%3}, {%4,%5,%6,%7}, {%8,%9}, {%0,%1,%2,%3};"
                 : "+f"(c[0]), "+f"(c[1]), "+f"(c[2]), "+f"(c[3])
                 : "r"(a[0]), "r"(a[1]), "r"(a[2]), "r"(a[3]), "r"(b[0]), "r"(b[1]));
}
static __device__ __forceinline__ void split2(float x0, float x1, uint32_t& hi, uint32_t& lo) {
    uint32_t h;
    asm("cvt.rn.bf16x2.f32 %0, %1, %2;" : "=r"(h) : "f"(x1), "f"(x0));
    float h0 = __uint_as_float(h << 16);
    float h1 = __uint_as_float(h & 0xFFFF0000u);
    uint32_t l;
    asm("cvt.rn.bf16x2.f32 %0, %1, %2;" : "=r"(l) : "f"(x1 - h1), "f"(x0 - h0));
    hi = h; lo = l;
}
static __device__ __forceinline__ float* scratch_ptr(int row, int j) {
    if (j < 320) return g_UV + (size_t)row * 320 + j;
    if (j < 448) return g_G1 + (size_t)row * 128 + (j - 320);
    return g_G2 + (size_t)row * 128 + (j - 448);
}
static __device__ __forceinline__ float lut_eval(const float2* tab, float x) {
    float tp = fmaf(x, 512.0f / 20.0f, 256.0f);
    tp = fminf(fmaxf(tp, 0.0f), 511.5f);
    const float2 c = tab[(int)tp];
    return fmaf(tp, c.y, c.x);
}

// =====================================================================
// Kernel A (persistent): [NNODE,64] @ BigW[64,576] -> UV | G1 | G2
// =====================================================================
__global__ __launch_bounds__(A_THR, 1)
void node_gemm_kernel(const float* __restrict__ z,
                      const float* __restrict__ Wffw,
                      const float* __restrict__ Wf,
                      const float* __restrict__ Ws)
{
    extern __shared__ char sm[];
    const uint32_t sb = smem_u32(sm);
    const int tid = threadIdx.x, wid = tid >> 5, lane = tid & 31;
    const int mi = wid >> 2, ni = wid & 3;

    for (int idx = tid; idx < 64 * 576; idx += A_THR) {
        const int k = idx / 576, j = idx - k * 576;
        float w;
        if (j < 160)      w = Wffw[k * 160 + j];
        else if (j < 320) w = Wffw[(64 + k) * 160 + (j - 160)];
        else if (j < 384) w = Wf[k * 64 + (j - 320)];
        else if (j < 448) w = Ws[k * 64 + (j - 384)];
        else if (j < 512) w = Wf[(64 + k) * 64 + (j - 448)];
        else              w = Ws[(64 + k) * 64 + (j - 512)];
        const __nv_bfloat16 h = __float2bfloat16(w);
        const __nv_bfloat16 l = __float2bfloat16(w - __bfloat162float(h));
        *reinterpret_cast<__nv_bfloat16*>(sm + A_WH + k * A_WSTR + j * 2) = h;
        *reinterpret_cast<__nv_bfloat16*>(sm + A_WL + k * A_WSTR + j * 2) = l;
    }

    const int r = tid >> 3, cq = (tid & 7) * 8;

    float4 va = make_float4(0.f, 0.f, 0.f, 0.f), vb = va;
    int t = blockIdx.x;
    if (t < A_NT) {
        const int grow = t * A_TILE + r;
        if (grow < NNODE) {
            const float4* zr = reinterpret_cast<const float4*>(z + (size_t)grow * 64 + cq);
            va = zr[0]; vb = zr[1];
        }
    }

    for (; t < A_NT; t += gridDim.x) {
        __syncthreads();

        {
            uint32_t* zh = reinterpret_cast<uint32_t*>(sm + A_ZH + r * A_ZSTR + cq * 2);
            uint32_t* zl = reinterpret_cast<uint32_t*>(sm + A_ZL + r * A_ZSTR + cq * 2);
            uint32_t h0, l0, h1, l1;
            split2(va.x, va.y, h0, l0); split2(va.z, va.w, h1, l1);
            zh[0] = h0; zh[1] = h1; zl[0] = l0; zl[1] = l1;
            split2(vb.x, vb.y, h0, l0); split2(vb.z, vb.w, h1, l1);
            zh[2] = h0; zh[3] = h1; zl[2] = l0; zl[3] = l1;
        }
        __syncthreads();

        const int tn = t + gridDim.x;
        va = make_float4(0.f, 0.f, 0.f, 0.f); vb = va;
        if (tn < A_NT) {
            const int grow = tn * A_TILE + r;
            if (grow < NNODE) {
                const float4* zr = reinterpret_cast<const float4*>(z + (size_t)grow * 64 + cq);
                va = zr[0]; vb = zr[1];
            }
        }

        float acc[18][4];
        #pragma unroll
        for (int n = 0; n < 18; n++)
            #pragma unroll
            for (int q = 0; q < 4; q++) acc[n][q] = 0.0f;

        #pragma unroll
        for (int k = 0; k < 4; k++) {
            uint32_t ah[4], al[4];
            const uint32_t arow = (uint32_t)(mi * 16 + (lane & 15)) * A_ZSTR
                                + (uint32_t)k * 32 + ((lane >> 4) << 4);
            ldm_x4(ah, sb + A_ZH + arow);
            ldm_x4(al, sb + A_ZL + arow);
            const uint32_t brow = (uint32_t)(k * 16 + (lane & 15)) * A_WSTR + (uint32_t)ni * 288;
            #pragma unroll
            for (int n = 0; n < 18; n++) {
                uint32_t bh[2], bl[2];
                ldm_x2t(bh, sb + A_WH + brow + n * 16);
                ldm_x2t(bl, sb + A_WL + brow + n * 16);
                mma_bf16(acc[n], ah, bh);
                mma_bf16(acc[n], al, bh);
                mma_bf16(acc[n], ah, bl);
            }
        }

        const int r0 = t * A_TILE + mi * 16 + (lane >> 2);
        const int r1 = r0 + 8;
        #pragma unroll
        for (int n = 0; n < 18; n++) {
            const int j = ni * 144 + n * 8 + 2 * (lane & 3);
            if (r0 < NNODE) {
                float2 o; o.x = acc[n][0]; o.y = acc[n][1];
                *reinterpret_cast<float2*>(scratch_ptr(r0, j)) = o;
            }
            if (r1 < NNODE) {
                float2 o; o.x = acc[n][2]; o.y = acc[n][3];
                *reinterpret_cast<float2*>(scratch_ptr(r1, j)) = o;
            }
        }
    }
}

// =====================================================================
// Kernel F (fused): streaming traffic (ea in, z_edge out) uses evict-first
// cache hints so UV/G1/G2 gathers stay L2-resident.
// =====================================================================
__global__ __launch_bounds__(F_THR, 3)
void edge_gate_kernel(const float* __restrict__ ea,
                      const int*   __restrict__ srcp,
                      const int*   __restrict__ dstp,
                      const float* __restrict__ Wffw,
                      const float* __restrict__ bias,
                      const float* __restrict__ bf,
                      const float* __restrict__ bs,
                      float* __restrict__ z_edge,
                      float* __restrict__ z_node)
{
    extern __shared__ char sm[];
    const uint32_t sb = smem_u32(sm);
    const int tid = threadIdx.x, wid = tid >> 5, lane = tid & 31;
    const int mi = wid >> 2, ni = wid & 3;

    // ---- one-time init ----
    for (int idx = tid; idx < 32 * 160; idx += F_THR) {
        const int k = idx / 160, n = idx - k * 160;
        const float w = Wffw[(128 + k) * 160 + n];
        const __nv_bfloat16 h = __float2bfloat16(w);
        const __nv_bfloat16 l = __float2bfloat16(w - __bfloat162float(h));
        *reinterpret_cast<__nv_bfloat16*>(sm + F_WH + k * F_WSTR + n * 2) = h;
        *reinterpret_cast<__nv_bfloat16*>(sm + F_WL + k * F_WSTR + n * 2) = l;
    }
    if (tid < 160) reinterpret_cast<float*>(sm + F_BIAS)[tid] = bias[tid];
    for (int i = tid; i < 512; i += F_THR) {
        const float x0 = -10.0f + (float)i * (20.0f / 512.0f);
        const float x1 = x0 + (20.0f / 512.0f);
        const float s0 = 1.0f / (1.0f + expf(-x0));
        const float s1 = 1.0f / (1.0f + expf(-x1));
        const float ds = s1 - s0;
        reinterpret_cast<float2*>(sm + F_LSIG)[i] = make_float2(s0 - (float)i * ds, ds);
        const float p0 = fmaxf(x0, 0.0f) + log1pf(expf(-fabsf(x0)));
        const float p1 = fmaxf(x1, 0.0f) + log1pf(expf(-fabsf(x1)));
        const float dp = p1 - p0;
        reinterpret_cast<float2*>(sm + F_LSP)[i] = make_float2(p0 - (float)i * dp, dp);
    }
    if (tid < 64) {
        reinterpret_cast<float*>(sm + F_BF)[tid] = bf[tid];
        reinterpret_cast<float*>(sm + F_BS)[tid] = bs[tid];
    }

    const float*  s_bias = reinterpret_cast<const float*>(sm + F_BIAS);
    const float2* t_sig  = reinterpret_cast<const float2*>(sm + F_LSIG);
    const float2* t_sp   = reinterpret_cast<const float2*>(sm + F_LSP);
    const float*  s_bf   = reinterpret_cast<const float*>(sm + F_BF);
    const float*  s_bs   = reinterpret_cast<const float*>(sm + F_BS);

    const int e_q = tid >> 2, q = tid & 3;
    const int e_o = tid >> 3, oct = tid & 7;

    for (int t = blockIdx.x; t < F_NT; t += gridDim.x) {
        __syncthreads();

        // ---- phase 1: ea tile -> smem (streaming loads) ----
        {
            const int ge = t * F_TILE + e_q;
            const float4* ep = reinterpret_cast<const float4*>(ea + (size_t)ge * 32) + q * 2;
            const float4 a = __ldcs(ep);
            const float4 b = __ldcs(ep + 1);
            uint32_t* xh = reinterpret_cast<uint32_t*>(sm + F_EH + e_q * F_ESTR + q * 16);
            uint32_t* xl = reinterpret_cast<uint32_t*>(sm + F_EL + e_q * F_ESTR + q * 16);
            uint32_t h0, l0, h1, l1;
            split2(a.x, a.y, h0, l0); split2(a.z, a.w, h1, l1);
            xh[0] = h0; xh[1] = h1; xl[0] = l0; xl[1] = l1;
            split2(b.x, b.y, h0, l0); split2(b.z, b.w, h1, l1);
            xh[2] = h0; xh[3] = h1; xl[2] = l0; xl[3] = l1;
        }
        __syncthreads();

        // ---- phase 2: GEMM ea@W3 (K=32) ----
        float acc[2][5][4];
        #pragma unroll
        for (int m = 0; m < 2; m++)
            #pragma unroll
            for (int n = 0; n < 5; n++)
                #pragma unroll
                for (int r = 0; r < 4; r++) acc[m][n][r] = 0.0f;

        #pragma unroll
        for (int k = 0; k < 2; k++) {
            uint32_t ah[2][4], al[2][4];
            const uint32_t arow = (uint32_t)(mi * 32 + (lane & 15)) * F_ESTR
                                + (uint32_t)k * 32 + ((lane >> 4) << 4);
            #pragma unroll
            for (int m = 0; m < 2; m++) {
                ldm_x4(ah[m], sb + F_EH + arow + m * 16 * F_ESTR);
                ldm_x4(al[m], sb + F_EL + arow + m * 16 * F_ESTR);
            }
            const uint32_t brow = (uint32_t)(k * 16 + (lane & 15)) * F_WSTR + (uint32_t)ni * 80;
            #pragma unroll
            for (int n = 0; n < 5; n++) {
                uint32_t bh[2], bl[2];
                ldm_x2t(bh, sb + F_WH + brow + n * 16);
                ldm_x2t(bl, sb + F_WL + brow + n * 16);
                #pragma unroll
                for (int m = 0; m < 2; m++) {
                    mma_bf16(acc[m][n], ah[m], bh);
                    mma_bf16(acc[m][n], al[m], bh);
                    mma_bf16(acc[m][n], ah[m], bl);
                }
            }
        }
        __syncthreads();

        // ---- phase 3a: stage acc -> D tile (smem) ----
        {
            float* D = reinterpret_cast<float*>(sm + F_UNI);
            #pragma unroll
            for (int m = 0; m < 2; m++) {
                const int row = mi * 32 + m * 16 + (lane >> 2);
                #pragma unroll
                for (int n = 0; n < 5; n++) {
                    const int j = ni * 40 + n * 8 + 2 * (lane & 3);
                    float2 o0, o1;
                    o0.x = acc[m][n][0]; o0.y = acc[m][n][1];
                    o1.x = acc[m][n][2]; o1.y = acc[m][n][3];
                    *reinterpret_cast<float2*>(D + row * F_DSTR + j) = o0;
                    *reinterpret_cast<float2*>(D + (row + 8) * F_DSTR + j) = o1;
                }
            }
        }
        __syncthreads();

        // ---- phase 3b: coalesced epilogue; z_edge stores are streaming ----
        #pragma unroll
        for (int eh = 0; eh < 2; eh++) {
            const int le = e_o + 32 * eh;
            const int ge = t * F_TILE + le;
            const int s = srcp[ge], d = dstp[ge];
            const float4* U = reinterpret_cast<const float4*>(g_UV + (size_t)s * 320);
            const float4* V = reinterpret_cast<const float4*>(g_UV + (size_t)d * 320 + 160);
            const float4* D = reinterpret_cast<const float4*>(sm + F_UNI) + le * (F_DSTR / 4);
            const float4* B = reinterpret_cast<const float4*>(s_bias);
            float4* O = reinterpret_cast<float4*>(z_edge + (size_t)ge * 160);

            float4 u[5], v[5];
            #pragma unroll
            for (int i = 0; i < 5; i++) u[i] = U[oct + 8 * i];
            #pragma unroll
            for (int i = 0; i < 5; i++) v[i] = V[oct + 8 * i];
            #pragma unroll
            for (int i = 0; i < 5; i++) {
                const int c4 = oct + 8 * i;
                const float4 dd = D[c4], bb = B[c4];
                float4 o;
                o.x = fmaxf(dd.x + u[i].x + v[i].x + bb.x, 0.0f);
                o.y = fmaxf(dd.y + u[i].y + v[i].y + bb.y, 0.0f);
                o.z = fmaxf(dd.z + u[i].z + v[i].z + bb.z, 0.0f);
                o.w = fmaxf(dd.w + u[i].w + v[i].w + bb.w, 0.0f);
                __stcs(&O[c4], o);
            }

            // ---- phase 4: gate + scatter for the same edge ----
            const float4* Pf = reinterpret_cast<const float4*>(g_G1 + (size_t)d * 128);
            const float4* Qf = reinterpret_cast<const float4*>(g_G2 + (size_t)s * 128);
            const float4* Ps = Pf + 16;
            const float4* Qs = Qf + 16;
            const float4* Bf = reinterpret_cast<const float4*>(s_bf);
            const float4* Bs = reinterpret_cast<const float4*>(s_bs);
            float4* out = reinterpret_cast<float4*>(z_node + (size_t)d * 64);

            float4 pf[2], qf[2], ps[2], qs[2];
            #pragma unroll
            for (int i = 0; i < 2; i++) pf[i] = Pf[oct + 8 * i];
            #pragma unroll
            for (int i = 0; i < 2; i++) qf[i] = Qf[oct + 8 * i];
            #pragma unroll
            for (int i = 0; i < 2; i++) ps[i] = Ps[oct + 8 * i];
            #pragma unroll
            for (int i = 0; i < 2; i++) qs[i] = Qs[oct + 8 * i];

            #pragma unroll
            for (int i = 0; i < 2; i++) {
                const int c4 = oct + 8 * i;
                const float4 bfv = Bf[c4], bsv = Bs[c4];
                float4 msg;
                {
                    const float f = pf[i].x + qf[i].x + bfv.x;
                    const float vv = ps[i].x + qs[i].x + bsv.x;
                    msg.x = lut_eval(t_sig, f) * fmaxf(lut_eval(t_sp, vv), vv);
                }
                {
                    const float f = pf[i].y + qf[i].y + bfv.y;
                    const float vv = ps[i].y + qs[i].y + bsv.y;
                    msg.y = lut_eval(t_sig, f) * fmaxf(lut_eval(t_sp, vv), vv);
                }
                {
                    const float f = pf[i].z + qf[i].z + bfv.z;
                    const float vv = ps[i].z + qs[i].z + bsv.z;
                    msg.z = lut_eval(t_sig, f) * fmaxf(lut_eval(t_sp, vv), vv);
                }
                {
                    const float f = pf[i].w + qf[i].w + bfv.w;
                    const float vv = ps[i].w + qs[i].w + bsv.w;
                    msg.w = lut_eval(t_sig, f) * fmaxf(lut_eval(t_sp, vv), vv);
                }
                atomicAdd(&out[c4], msg);
            }
        }
    }
}

extern "C" void kernel_launch(void* const* d_in, const int* in_sizes, int n_in,
                              void* d_out, int out_size)
{
    const float* z    = (const float*)d_in[0];
    const float* ea   = (const float*)d_in[1];
    const int*   eidx = (const int*)  d_in[2];
    const float* Wffw = (const float*)d_in[3];
    const float* bffw = (const float*)d_in[4];
    const float* Wf   = (const float*)d_in[5];
    const float* bf   = (const float*)d_in[6];
    const float* Ws   = (const float*)d_in[7];
    const float* bs   = (const float*)d_in[8];

    float* z_node = (float*)d_out;
    float* z_edge = (float*)d_out + (size_t)NNODE * 64;
    const int* srcp = eidx;
    const int* dstp = eidx + NE;

    static bool init = false;
    if (!init) {
        init = true;
        cudaFuncSetAttribute(node_gemm_kernel, cudaFuncAttributeMaxDynamicSharedMemorySize, A_SMEM);
        cudaFuncSetAttribute(edge_gate_kernel, cudaFuncAttributeMaxDynamicSharedMemorySize, F_SMEM);
    }

    // residual base for scatter-add
    cudaMemcpyAsync(z_node, z, (size_t)NNODE * 64 * sizeof(float),
                    cudaMemcpyDeviceToDevice, 0);
    node_gemm_kernel<<<148, A_THR, A_SMEM, 0>>>(z, Wffw, Wf, Ws);
    edge_gate_kernel<<<444, F_THR, F_SMEM, 0>>>(ea, srcp, dstp, Wffw, bffw,
                                                bf, bs, z_edge, z_node);
}

// round 14
// speedup vs baseline: 1.7308x; 1.0718x over previous
#include <cuda_runtime.h>
#include <cuda_bf16.h>
#include <cstdint>
#include <math.h>

#define NE      800000
#define NNODE   50000

// ---------------- scratch (static device arrays; no allocation) ----------------
__device__ float g_UV[(size_t)NNODE * 320];   // [n][0:160]=U=z@W1, [160:320]=V=z@W2
__device__ float g_G1[(size_t)NNODE * 128];   // [n][0:64]=P, [64:128]=R
__device__ float g_G2[(size_t)NNODE * 128];   // [n][0:64]=Q, [64:128]=S
__device__ int   g_cnt[NNODE];                // histogram by dst
__device__ int   g_off[NNODE];                // running bucket offsets
__device__ int   g_perm[NE];                  // sorted order -> original edge id
__device__ int   g_esrc[NE];                  // src of sorted edge
__device__ int   g_edst[NE];                  // dst of sorted edge

// ---------------- kernel A (node GEMM, persistent) ----------------
#define A_THR  512
#define A_TILE 64
#define A_NT   ((NNODE + A_TILE - 1) / A_TILE)
#define A_ZSTR 144
#define A_WSTR 1168
#define A_ZH   0
#define A_ZL   (A_ZH + 64 * A_ZSTR)
#define A_WH   (A_ZL + 64 * A_ZSTR)
#define A_WL   (A_WH + 64 * A_WSTR)
#define A_SMEM (A_WL + 64 * A_WSTR)              // 167936

// ---------------- kernel F ----------------
#define F_THR   256
#define F_TILE  64
#define F_NT    (NE / F_TILE)                    // 12500
#define F_ESTR  80
#define F_WSTR  336
#define F_DSTR  168
#define F_WH    0
#define F_WL    (F_WH + 32 * F_WSTR)
#define F_BIAS  (F_WL + 32 * F_WSTR)
#define F_LSIG  (F_BIAS + 640)
#define F_LSP   (F_LSIG + 4096)
#define F_BF    (F_LSP + 4096)
#define F_BS    (F_BF + 256)
#define F_UNI   (F_BS + 256)
#define F_EH    (F_UNI)
#define F_EL    (F_UNI + 64 * F_ESTR)
#define F_SMEM  (F_UNI + 64 * F_DSTR * 4)        // 73856 -> 3 CTAs/SM

static __device__ __forceinline__ uint32_t smem_u32(const void* p) {
    uint32_t a;
    asm("{ .reg .u64 t; cvta.to.shared.u64 t, %1; cvt.u32.u64 %0, t; }" : "=r"(a) : "l"(p));
    return a;
}
static __device__ __forceinline__ void ldm_x4(uint32_t* r, uint32_t addr) {
    asm volatile("ldmatrix.sync.aligned.m8n8.x4.shared.b16 {%0,%1,%2,%3}, [%4];"
                 : "=r"(r[0]), "=r"(r[1]), "=r"(r[2]), "=r"(r[3]) : "r"(addr));
}
static __device__ __forceinline__ void ldm_x2t(uint32_t* r, uint32_t addr) {
    asm volatile("ldmatrix.sync.aligned.m8n8.x2.trans.shared.b16 {%0,%1}, [%2];"
                 : "=r"(r[0]), "=r"(r[1]) : "r"(addr));
}
static __device__ __forceinline__ void mma_bf16(float* c, const uint32_t* a, const uint32_t* b) {
    asm volatile("mma.sync.aligned.m16n8k16.row.col.f32.bf16.bf16.f32 "
                 "{%0,%1,%2,%3}, {%4,%5,%6,%7}, {%8,%9}, {%0,%1,%2,%3};"
                 : "+f"(c[0]), "+f"(c[1]), "+f"(c[2]), "+f"(c[3])
                 : "r"(a[0]), "r"(a[1]), "r"(a[2]), "r"(a[3]), "r"(b[0]), "r"(b[1]));
}
static __device__ __forceinline__ void split2(float x0, float x1, uint32_t& hi, uint32_t& lo) {
    uint32_t h;
    asm("cvt.rn.bf16x2.f32 %0, %1, %2;" : "=r"(h) : "f"(x1), "f"(x0));
    float h0 = __uint_as_float(h << 16);
    float h1 = __uint_as_float(h & 0xFFFF0000u);
    uint32_t l;
    asm("cvt.rn.bf16x2.f32 %0, %1, %2;" : "=r"(l) : "f"(x1 - h1), "f"(x0 - h0));
    hi = h; lo = l;
}
static __device__ __forceinline__ float* scratch_ptr(int row, int j) {
    if (j < 320) return g_UV + (size_t)row * 320 + j;
    if (j < 448) return g_G1 + (size_t)row * 128 + (j - 320);
    return g_G2 + (size_t)row * 128 + (j - 448);
}
static __device__ __forceinline__ float lut_eval(const float2* tab, float x) {
    float tp = fmaf(x, 512.0f / 20.0f, 256.0f);
    tp = fminf(fmaxf(tp, 0.0f), 511.5f);
    const float2 c = tab[(int)tp];
    return fmaf(tp, c.y, c.x);
}

// =====================================================================
// Sort kernels: counting sort of edges by dst
// =====================================================================
__global__ void sort_zero_kernel() {
    const int i = blockIdx.x * 256 + threadIdx.x;
    if (i < NNODE) g_cnt[i] = 0;
}
__global__ void sort_hist_kernel(const int* __restrict__ dstp) {
    const int e = blockIdx.x * 256 + threadIdx.x;
    if (e < NE) atomicAdd(&g_cnt[dstp[e]], 1);
}
__global__ __launch_bounds__(1024) void sort_scan_kernel() {
    __shared__ int part[1024];
    const int tid = threadIdx.x;
    const int CH = (NNODE + 1023) / 1024;   // 49
    const int base = tid * CH;
    int sum = 0;
    for (int i = 0; i < CH; i++) {
        const int idx = base + i;
        if (idx < NNODE) sum += g_cnt[idx];
    }
    part[tid] = sum;
    __syncthreads();
    for (int d = 1; d < 1024; d <<= 1) {
        const int v = (tid >= d) ? part[tid - d] : 0;
        __syncthreads();
        part[tid] += v;
        __syncthreads();
    }
    int run = (tid == 0) ? 0 : part[tid - 1];
    for (int i = 0; i < CH; i++) {
        const int idx = base + i;
        if (idx < NNODE) {
            g_off[idx] = run;
            run += g_cnt[idx];
        }
    }
}
__global__ void sort_scatter_kernel(const int* __restrict__ srcp,
                                    const int* __restrict__ dstp) {
    const int e = blockIdx.x * 256 + threadIdx.x;
    if (e < NE) {
        const int d = dstp[e];
        const int pos = atomicAdd(&g_off[d], 1);
        g_perm[pos] = e;
        g_esrc[pos] = srcp[e];
        g_edst[pos] = d;
    }
}

// =====================================================================
// Kernel A (persistent): [NNODE,64] @ BigW[64,576] -> UV | G1 | G2
// =====================================================================
__global__ __launch_bounds__(A_THR, 1)
void node_gemm_kernel(const float* __restrict__ z,
                      const float* __restrict__ Wffw,
                      const float* __restrict__ Wf,
                      const float* __restrict__ Ws)
{
    extern __shared__ char sm[];
    const uint32_t sb = smem_u32(sm);
    const int tid = threadIdx.x, wid = tid >> 5, lane = tid & 31;
    const int mi = wid >> 2, ni = wid & 3;

    for (int idx = tid; idx < 64 * 576; idx += A_THR) {
        const int k = idx / 576, j = idx - k * 576;
        float w;
        if (j < 160)      w = Wffw[k * 160 + j];
        else if (j < 320) w = Wffw[(64 + k) * 160 + (j - 160)];
        else if (j < 384) w = Wf[k * 64 + (j - 320)];
        else if (j < 448) w = Ws[k * 64 + (j - 384)];
        else if (j < 512) w = Wf[(64 + k) * 64 + (j - 448)];
        else              w = Ws[(64 + k) * 64 + (j - 512)];
        const __nv_bfloat16 h = __float2bfloat16(w);
        const __nv_bfloat16 l = __float2bfloat16(w - __bfloat162float(h));
        *reinterpret_cast<__nv_bfloat16*>(sm + A_WH + k * A_WSTR + j * 2) = h;
        *reinterpret_cast<__nv_bfloat16*>(sm + A_WL + k * A_WSTR + j * 2) = l;
    }

    const int r = tid >> 3, cq = (tid & 7) * 8;

    float4 va = make_float4(0.f, 0.f, 0.f, 0.f), vb = va;
    int t = blockIdx.x;
    if (t < A_NT) {
        const int grow = t * A_TILE + r;
        if (grow < NNODE) {
            const float4* zr = reinterpret_cast<const float4*>(z + (size_t)grow * 64 + cq);
            va = zr[0]; vb = zr[1];
        }
    }

    for (; t < A_NT; t += gridDim.x) {
        __syncthreads();

        {
            uint32_t* zh = reinterpret_cast<uint32_t*>(sm + A_ZH + r * A_ZSTR + cq * 2);
            uint32_t* zl = reinterpret_cast<uint32_t*>(sm + A_ZL + r * A_ZSTR + cq * 2);
            uint32_t h0, l0, h1, l1;
            split2(va.x, va.y, h0, l0); split2(va.z, va.w, h1, l1);
            zh[0] = h0; zh[1] = h1; zl[0] = l0; zl[1] = l1;
            split2(vb.x, vb.y, h0, l0); split2(vb.z, vb.w, h1, l1);
            zh[2] = h0; zh[3] = h1; zl[2] = l0; zl[3] = l1;
        }
        __syncthreads();

        const int tn = t + gridDim.x;
        va = make_float4(0.f, 0.f, 0.f, 0.f); vb = va;
        if (tn < A_NT) {
            const int grow = tn * A_TILE + r;
            if (grow < NNODE) {
                const float4* zr = reinterpret_cast<const float4*>(z + (size_t)grow * 64 + cq);
                va = zr[0]; vb = zr[1];
            }
        }

        float acc[18][4];
        #pragma unroll
        for (int n = 0; n < 18; n++)
            #pragma unroll
            for (int q = 0; q < 4; q++) acc[n][q] = 0.0f;

        #pragma unroll
        for (int k = 0; k < 4; k++) {
            uint32_t ah[4], al[4];
            const uint32_t arow = (uint32_t)(mi * 16 + (lane & 15)) * A_ZSTR
                                + (uint32_t)k * 32 + ((lane >> 4) << 4);
            ldm_x4(ah, sb + A_ZH + arow);
            ldm_x4(al, sb + A_ZL + arow);
            const uint32_t brow = (uint32_t)(k * 16 + (lane & 15)) * A_WSTR + (uint32_t)ni * 288;
            #pragma unroll
            for (int n = 0; n < 18; n++) {
                uint32_t bh[2], bl[2];
                ldm_x2t(bh, sb + A_WH + brow + n * 16);
                ldm_x2t(bl, sb + A_WL + brow + n * 16);
                mma_bf16(acc[n], ah, bh);
                mma_bf16(acc[n], al, bh);
                mma_bf16(acc[n], ah, bl);
            }
        }

        const int r0 = t * A_TILE + mi * 16 + (lane >> 2);
        const int r1 = r0 + 8;
        #pragma unroll
        for (int n = 0; n < 18; n++) {
            const int j = ni * 144 + n * 8 + 2 * (lane & 3);
            if (r0 < NNODE) {
                float2 o; o.x = acc[n][0]; o.y = acc[n][1];
                *reinterpret_cast<float2*>(scratch_ptr(r0, j)) = o;
            }
            if (r1 < NNODE) {
                float2 o; o.x = acc[n][2]; o.y = acc[n][3];
                *reinterpret_cast<float2*>(scratch_ptr(r1, j)) = o;
            }
        }
    }
}

// =====================================================================
// Kernel F (fused, dst-sorted edge order): per sorted 64-edge tile
//   z_edge[perm[i]] = relu(U[src] + V[dst] + ea[perm[i]]@W3 + b)
//   z_node[dst]    += sigmoid(P[dst]+Q[src]+bf) * softplus(R[dst]+S[src]+bs)
// =====================================================================
__global__ __launch_bounds__(F_THR, 3)
void edge_gate_kernel(const float* __restrict__ ea,
                      const float* __restrict__ Wffw,
                      const float* __restrict__ bias,
                      const float* __restrict__ bf,
                      const float* __restrict__ bs,
                      float* __restrict__ z_edge,
                      float* __restrict__ z_node)
{
    extern __shared__ char sm[];
    const uint32_t sb = smem_u32(sm);
    const int tid = threadIdx.x, wid = tid >> 5, lane = tid & 31;
    const int mi = wid >> 2, ni = wid & 3;

    // ---- one-time init ----
    for (int idx = tid; idx < 32 * 160; idx += F_THR) {
        const int k = idx / 160, n = idx - k * 160;
        const float w = Wffw[(128 + k) * 160 + n];
        const __nv_bfloat16 h = __float2bfloat16(w);
        const __nv_bfloat16 l = __float2bfloat16(w - __bfloat162float(h));
        *reinterpret_cast<__nv_bfloat16*>(sm + F_WH + k * F_WSTR + n * 2) = h;
        *reinterpret_cast<__nv_bfloat16*>(sm + F_WL + k * F_WSTR + n * 2) = l;
    }
    if (tid < 160) reinterpret_cast<float*>(sm + F_BIAS)[tid] = bias[tid];
    for (int i = tid; i < 512; i += F_THR) {
        const float x0 = -10.0f + (float)i * (20.0f / 512.0f);
        const float x1 = x0 + (20.0f / 512.0f);
        const float s0 = 1.0f / (1.0f + expf(-x0));
        const float s1 = 1.0f / (1.0f + expf(-x1));
        const float ds = s1 - s0;
        reinterpret_cast<float2*>(sm + F_LSIG)[i] = make_float2(s0 - (float)i * ds, ds);
        const float p0 = fmaxf(x0, 0.0f) + log1pf(expf(-fabsf(x0)));
        const float p1 = fmaxf(x1, 0.0f) + log1pf(expf(-fabsf(x1)));
        const float dp = p1 - p0;
        reinterpret_cast<float2*>(sm + F_LSP)[i] = make_float2(p0 - (float)i * dp, dp);
    }
    if (tid < 64) {
        reinterpret_cast<float*>(sm + F_BF)[tid] = bf[tid];
        reinterpret_cast<float*>(sm + F_BS)[tid] = bs[tid];
    }

    const float*  s_bias = reinterpret_cast<const float*>(sm + F_BIAS);
    const float2* t_sig  = reinterpret_cast<const float2*>(sm + F_LSIG);
    const float2* t_sp   = reinterpret_cast<const float2*>(sm + F_LSP);
    const float*  s_bf   = reinterpret_cast<const float*>(sm + F_BF);
    const float*  s_bs   = reinterpret_cast<const float*>(sm + F_BS);

    const int e_q = tid >> 2, q = tid & 3;
    const int e_o = tid >> 3, oct = tid & 7;

    for (int t = blockIdx.x; t < F_NT; t += gridDim.x) {
        __syncthreads();

        // ---- phase 1: ea tile (via perm) -> smem ----
        {
            const int pe = g_perm[t * F_TILE + e_q];
            const float4* ep = reinterpret_cast<const float4*>(ea + (size_t)pe * 32) + q * 2;
            const float4 a = __ldcs(ep);
            const float4 b = __ldcs(ep + 1);
            uint32_t* xh = reinterpret_cast<uint32_t*>(sm + F_EH + e_q * F_ESTR + q * 16);
            uint32_t* xl = reinterpret_cast<uint32_t*>(sm + F_EL + e_q * F_ESTR + q * 16);
            uint32_t h0, l0, h1, l1;
            split2(a.x, a.y, h0, l0); split2(a.z, a.w, h1, l1);
            xh[0] = h0; xh[1] = h1; xl[0] = l0; xl[1] = l1;
            split2(b.x, b.y, h0, l0); split2(b.z, b.w, h1, l1);
            xh[2] = h0; xh[3] = h1; xl[2] = l0; xl[3] = l1;
        }
        __syncthreads();

        // ---- phase 2: GEMM ea@W3 (K=32) ----
        float acc[2][5][4];
        #pragma unroll
        for (int m = 0; m < 2; m++)
            #pragma unroll
            for (int n = 0; n < 5; n++)
                #pragma unroll
                for (int r = 0; r < 4; r++) acc[m][n][r] = 0.0f;

        #pragma unroll
        for (int k = 0; k < 2; k++) {
            uint32_t ah[2][4], al[2][4];
            const uint32_t arow = (uint32_t)(mi * 32 + (lane & 15)) * F_ESTR
                                + (uint32_t)k * 32 + ((lane >> 4) << 4);
            #pragma unroll
            for (int m = 0; m < 2; m++) {
                ldm_x4(ah[m], sb + F_EH + arow + m * 16 * F_ESTR);
                ldm_x4(al[m], sb + F_EL + arow + m * 16 * F_ESTR);
            }
            const uint32_t brow = (uint32_t)(k * 16 + (lane & 15)) * F_WSTR + (uint32_t)ni * 80;
            #pragma unroll
            for (int n = 0; n < 5; n++) {
                uint32_t bh[2], bl[2];
                ldm_x2t(bh, sb + F_WH + brow + n * 16);
                ldm_x2t(bl, sb + F_WL + brow + n * 16);
                #pragma unroll
                for (int m = 0; m < 2; m++) {
                    mma_bf16(acc[m][n], ah[m], bh);
                    mma_bf16(acc[m][n], al[m], bh);
                    mma_bf16(acc[m][n], ah[m], bl);
                }
            }
        }
        __syncthreads();

        // ---- phase 3a: stage acc -> D tile (smem) ----
        {
            float* D = reinterpret_cast<float*>(sm + F_UNI);
            #pragma unroll
            for (int m = 0; m < 2; m++) {
                const int row = mi * 32 + m * 16 + (lane >> 2);
                #pragma unroll
                for (int n = 0; n < 5; n++) {
                    const int j = ni * 40 + n * 8 + 2 * (lane & 3);
                    float2 o0, o1;
                    o0.x = acc[m][n][0]; o0.y = acc[m][n][1];
                    o1.x = acc[m][n][2]; o1.y = acc[m][n][3];
                    *reinterpret_cast<float2*>(D + row * F_DSTR + j) = o0;
                    *reinterpret_cast<float2*>(D + (row + 8) * F_DSTR + j) = o1;
                }
            }
        }
        __syncthreads();

        // ---- phase 3b + 4: coalesced epilogues over sorted edges ----
        #pragma unroll
        for (int eh = 0; eh < 2; eh++) {
            const int le = e_o + 32 * eh;
            const int si = t * F_TILE + le;
            const int pe = g_perm[si];
            const int s  = g_esrc[si];
            const int d  = g_edst[si];

            const float4* U = reinterpret_cast<const float4*>(g_UV + (size_t)s * 320);
            const float4* V = reinterpret_cast<const float4*>(g_UV + (size_t)d * 320 + 160);
            const float4* D = reinterpret_cast<const float4*>(sm + F_UNI) + le * (F_DSTR / 4);
            const float4* B = reinterpret_cast<const float4*>(s_bias);
            float4* O = reinterpret_cast<float4*>(z_edge + (size_t)pe * 160);

            float4 u[5], v[5];
            #pragma unroll
            for (int i = 0; i < 5; i++) u[i] = U[oct + 8 * i];
            #pragma unroll
            for (int i = 0; i < 5; i++) v[i] = V[oct + 8 * i];
            #pragma unroll
            for (int i = 0; i < 5; i++) {
                const int c4 = oct + 8 * i;
                const float4 dd = D[c4], bb = B[c4];
                float4 o;
                o.x = fmaxf(dd.x + u[i].x + v[i].x + bb.x, 0.0f);
                o.y = fmaxf(dd.y + u[i].y + v[i].y + bb.y, 0.0f);
                o.z = fmaxf(dd.z + u[i].z + v[i].z + bb.z, 0.0f);
                o.w = fmaxf(dd.w + u[i].w + v[i].w + bb.w, 0.0f);
                __stcs(&O[c4], o);
            }

            const float4* Pf = reinterpret_cast<const float4*>(g_G1 + (size_t)d * 128);
            const float4* Qf = reinterpret_cast<const float4*>(g_G2 + (size_t)s * 128);
            const float4* Ps = Pf + 16;
            const float4* Qs = Qf + 16;
            const float4* Bf = reinterpret_cast<const float4*>(s_bf);
            const float4* Bs = reinterpret_cast<const float4*>(s_bs);
            float4* out = reinterpret_cast<float4*>(z_node + (size_t)d * 64);

            float4 pf[2], qf[2], ps[2], qs[2];
            #pragma unroll
            for (int i = 0; i < 2; i++) pf[i] = Pf[oct + 8 * i];
            #pragma unroll
            for (int i = 0; i < 2; i++) qf[i] = Qf[oct + 8 * i];
            #pragma unroll
            for (int i = 0; i < 2; i++) ps[i] = Ps[oct + 8 * i];
            #pragma unroll
            for (int i = 0; i < 2; i++) qs[i] = Qs[oct + 8 * i];

            #pragma unroll
            for (int i = 0; i < 2; i++) {
                const int c4 = oct + 8 * i;
                const float4 bfv = Bf[c4], bsv = Bs[c4];
                float4 msg;
                {
                    const float f = pf[i].x + qf[i].x + bfv.x;
                    const float vv = ps[i].x + qs[i].x + bsv.x;
                    msg.x = lut_eval(t_sig, f) * fmaxf(lut_eval(t_sp, vv), vv);
                }
                {
                    const float f = pf[i].y + qf[i].y + bfv.y;
                    const float vv = ps[i].y + qs[i].y + bsv.y;
                    msg.y = lut_eval(t_sig, f) * fmaxf(lut_eval(t_sp, vv), vv);
                }
                {
                    const float f = pf[i].z + qf[i].z + bfv.z;
                    const float vv = ps[i].z + qs[i].z + bsv.z;
                    msg.z = lut_eval(t_sig, f) * fmaxf(lut_eval(t_sp, vv), vv);
                }
                {
                    const float f = pf[i].w + qf[i].w + bfv.w;
                    const float vv = ps[i].w + qs[i].w + bsv.w;
                    msg.w = lut_eval(t_sig, f) * fmaxf(lut_eval(t_sp, vv), vv);
                }
                atomicAdd(&out[c4], msg);
            }
        }
    }
}

extern "C" void kernel_launch(void* const* d_in, const int* in_sizes, int n_in,
                              void* d_out, int out_size)
{
    const float* z    = (const float*)d_in[0];
    const float* ea   = (const float*)d_in[1];
    const int*   eidx = (const int*)  d_in[2];
    const float* Wffw = (const float*)d_in[3];
    const float* bffw = (const float*)d_in[4];
    const float* Wf   = (const float*)d_in[5];
    const float* bf   = (const float*)d_in[6];
    const float* Ws   = (const float*)d_in[7];
    const float* bs   = (const float*)d_in[8];

    float* z_node = (float*)d_out;
    float* z_edge = (float*)d_out + (size_t)NNODE * 64;
    const int* srcp = eidx;
    const int* dstp = eidx + NE;

    static bool init = false;
    if (!init) {
        init = true;
        cudaFuncSetAttribute(node_gemm_kernel, cudaFuncAttributeMaxDynamicSharedMemorySize, A_SMEM);
        cudaFuncSetAttribute(edge_gate_kernel, cudaFuncAttributeMaxDynamicSharedMemorySize, F_SMEM);
    }

    // residual base for scatter-add
    cudaMemcpyAsync(z_node, z, (size_t)NNODE * 64 * sizeof(float),
                    cudaMemcpyDeviceToDevice, 0);

    // counting sort of edges by dst
    sort_zero_kernel<<<(NNODE + 255) / 256, 256>>>();
    sort_hist_kernel<<<(NE + 255) / 256, 256>>>(dstp);
    sort_scan_kernel<<<1, 1024>>>();
    sort_scatter_kernel<<<(NE + 255) / 256, 256>>>(srcp, dstp);

    node_gemm_kernel<<<148, A_THR, A_SMEM, 0>>>(z, Wffw, Wf, Ws);
    edge_gate_kernel<<<444, F_THR, F_SMEM, 0>>>(ea, Wffw, bffw, bf, bs, z_edge, z_node);
}